// round 10
// baseline (speedup 1.0000x reference)
#include <cuda_runtime.h>
#include <cuda_bf16.h>
#include <math.h>
#include <stdint.h>

// ---------------------------------------------------------------------------
// DilatedAttention via mma.sync bf16 (3-pass error-compensated split),
// pure-bf16 GEMMs with cp.async 3-stage pipeline; all fp32->bf16 hi/lo
// splitting hoisted into one-shot convert kernels / fused epilogues.
// Scratch buffers aliased across phases to minimize static footprint.
//   B=4, L=8192, D=768, SEG=2048, RATE=4 -> Ls=2048/batch, MTOT=8192
// ---------------------------------------------------------------------------

#define B_      4
#define L_      8192
#define D_      768
#define LS_     2048
#define MTOT    (B_ * LS_)

typedef __nv_bfloat16 bf16;

// ---------------- device scratch (allocation-free rule) --------------------
// xq/xk planes are reused for LayerNormed q/k planes (phase-disjoint).
__device__ bf16  g_xqh[(long)MTOT * D_], g_xql[(long)MTOT * D_];
__device__ bf16  g_xkh[(long)MTOT * D_], g_xkl[(long)MTOT * D_];
__device__ bf16  g_xvh[(long)MTOT * D_], g_xvl[(long)MTOT * D_];
__device__ bf16  g_wqh[(long)D_ * D_],   g_wql[(long)D_ * D_];
__device__ bf16  g_wkh[(long)D_ * D_],   g_wkl[(long)D_ * D_];
__device__ bf16  g_wvh[(long)D_ * D_],   g_wvl[(long)D_ * D_];
__device__ float g_q[(long)MTOT * D_];          // q proj, later reused for O
__device__ float g_k[(long)MTOT * D_];
__device__ bf16  g_vth[(long)B_ * D_ * LS_], g_vtl[(long)B_ * D_ * LS_];
__device__ float g_s[(long)B_ * LS_ * LS_];     // 64 MB scores
__device__ bf16  g_ph[(long)B_ * LS_ * LS_], g_pl[(long)B_ * LS_ * LS_];

// ---------------- smem geometry -------------------------------------------
#define BM      128
#define BN      128
#define BKF     32                   // K per stage (elements)
#define ROWB    80                   // 64B data + 16B pad (LDSM conflict-free)
#define PLANE   (128 * ROWB)         // 10240 B
#define STAGE_B (4 * PLANE)          // Ah, Al, Bh, Bl = 40960 B
#define STAGES  3
#define SMEMSZ  (STAGES * STAGE_B)   // 122880 B

__device__ __forceinline__ uint32_t smem_u32(const void* p) {
    uint32_t a;
    asm("{ .reg .u64 t; cvta.to.shared.u64 t, %1; cvt.u32.u64 %0, t; }" : "=r"(a) : "l"(p));
    return a;
}

#define LDSM4(r, addr) \
    asm volatile("ldmatrix.sync.aligned.m8n8.x4.shared.b16 {%0,%1,%2,%3}, [%4];" \
        : "=r"((r)[0]), "=r"((r)[1]), "=r"((r)[2]), "=r"((r)[3]) : "r"(addr))

#define MMA_BF16(d, a, b) \
    asm volatile("mma.sync.aligned.m16n8k16.row.col.f32.bf16.bf16.f32 " \
        "{%0,%1,%2,%3}, {%4,%5,%6,%7}, {%8,%9}, {%0,%1,%2,%3};" \
        : "+f"((d)[0]), "+f"((d)[1]), "+f"((d)[2]), "+f"((d)[3]) \
        : "r"((a)[0]), "r"((a)[1]), "r"((a)[2]), "r"((a)[3]), "r"((b)[0]), "r"((b)[1]))

#define CP_ASYNC16(dst, src) \
    asm volatile("cp.async.cg.shared.global [%0], [%1], 16;" :: "r"(dst), "l"(src))
#define CP_COMMIT() asm volatile("cp.async.commit_group;" ::: "memory")
#define CP_WAIT1()  asm volatile("cp.async.wait_group 1;" ::: "memory")

__device__ __forceinline__ void split4(float4 v, uint2& hv, uint2& lv) {
    __nv_bfloat162 h01 = __floats2bfloat162_rn(v.x, v.y);
    __nv_bfloat162 h23 = __floats2bfloat162_rn(v.z, v.w);
    float lx = v.x - __bfloat162float(h01.x);
    float ly = v.y - __bfloat162float(h01.y);
    float lz = v.z - __bfloat162float(h23.x);
    float lw = v.w - __bfloat162float(h23.y);
    __nv_bfloat162 l01 = __floats2bfloat162_rn(lx, ly);
    __nv_bfloat162 l23 = __floats2bfloat162_rn(lz, lw);
    hv.x = *(uint32_t*)&h01; hv.y = *(uint32_t*)&h23;
    lv.x = *(uint32_t*)&l01; lv.y = *(uint32_t*)&l23;
}

// ---------------- cp.async stage fill: 2048 16B chunks, 8 per thread -------
__device__ __forceinline__ void issue_stage(
    const bf16* __restrict__ Ah, const bf16* __restrict__ Al,
    const bf16* __restrict__ Bh, const bf16* __restrict__ Bl,
    int ldA, int ldB, int bm0, int bn0, int k0,
    uint32_t smem_stage, int tid)
{
    #pragma unroll
    for (int i = 0; i < 8; i++) {
        const int plane = i >> 1;                // compile-time constant per i
        int w = (tid + (i << 8)) & 511;          // chunk within plane
        int r = w >> 2;
        int ck = w & 3;
        const bf16* src;
        if (plane == 0)      src = Ah + (long)(bm0 + r) * ldA + k0 + ck * 8;
        else if (plane == 1) src = Al + (long)(bm0 + r) * ldA + k0 + ck * 8;
        else if (plane == 2) src = Bh + (long)(bn0 + r) * ldB + k0 + ck * 8;
        else                 src = Bl + (long)(bn0 + r) * ldB + k0 + ck * 8;
        uint32_t dst = smem_stage + plane * PLANE + r * ROWB + ck * 16;
        CP_ASYNC16(dst, src);
    }
}

// ---------------- GEMM: C[128x128] = A[128xK] * B[128xK]^T (bf16 3-pass) ---
// OUTMODE 0: fp32 row-major C.  OUTMODE 1: vT split bf16 (Ch/Cl, per batch).
template<int OUTMODE>
__global__ void __launch_bounds__(256)
bf_gemm(const bf16* __restrict__ Ah, const bf16* __restrict__ Al,
        const bf16* __restrict__ Bh, const bf16* __restrict__ Bl,
        float* __restrict__ Cf, bf16* __restrict__ Ch, bf16* __restrict__ Cl,
        int K, float alpha, long sAb, long sBb, long sCb,
        int ldA, int ldB, int ldC)
{
    extern __shared__ char sm[];
    const uint32_t smem_base = smem_u32(sm);
    const int tid  = threadIdx.x;
    const int wid  = tid >> 5;
    const int lane = tid & 31;
    const int warpM = wid & 3;
    const int warpN = wid >> 2;
    const int bz = blockIdx.z;

    Ah += (long)bz * sAb;  Al += (long)bz * sAb;
    Bh += (long)bz * sBb;  Bl += (long)bz * sBb;

    const int bm0 = blockIdx.y * BM;
    const int bn0 = blockIdx.x * BN;
    const int NC  = K / BKF;

    float acc[2][8][4] = {};

    // prologue: stages 0,1
    issue_stage(Ah, Al, Bh, Bl, ldA, ldB, bm0, bn0, 0,   smem_base,           tid);
    CP_COMMIT();
    issue_stage(Ah, Al, Bh, Bl, ldA, ldB, bm0, bn0, BKF, smem_base + STAGE_B, tid);
    CP_COMMIT();

    const int aRow = warpM * 32 + (lane & 15);
    const int aKof = (lane >> 4) << 3;
    const int bRow = warpN * 64 + ((lane >> 4) << 3) + (lane & 7);
    const int bKof = ((lane >> 3) & 1) << 3;

    for (int c = 0; c < NC; c++) {
        CP_WAIT1();
        __syncthreads();

        if (c + 2 < NC)
            issue_stage(Ah, Al, Bh, Bl, ldA, ldB, bm0, bn0, (c + 2) * BKF,
                        smem_base + ((c + 2) % STAGES) * STAGE_B, tid);
        CP_COMMIT();

        const uint32_t sb  = smem_base + (c % STAGES) * STAGE_B;
        const uint32_t aHi = sb, aLo = sb + PLANE;
        const uint32_t bHi = sb + 2 * PLANE, bLo = sb + 3 * PLANE;

        #pragma unroll
        for (int k16 = 0; k16 < 2; k16++) {
            const int kk = k16 << 4;
            uint32_t ah[2][4], al[2][4], bh[8][2], bl[8][2];
            #pragma unroll
            for (int mt = 0; mt < 2; mt++) {
                uint32_t off = (uint32_t)((aRow + mt * 16) * ROWB + (kk + aKof) * 2);
                LDSM4(ah[mt], aHi + off);
                LDSM4(al[mt], aLo + off);
            }
            #pragma unroll
            for (int np = 0; np < 4; np++) {
                uint32_t off = (uint32_t)((bRow + np * 16) * ROWB + (kk + bKof) * 2);
                uint32_t r[4];
                LDSM4(r, bHi + off);
                bh[np*2][0] = r[0]; bh[np*2][1] = r[1];
                bh[np*2+1][0] = r[2]; bh[np*2+1][1] = r[3];
                LDSM4(r, bLo + off);
                bl[np*2][0] = r[0]; bl[np*2][1] = r[1];
                bl[np*2+1][0] = r[2]; bl[np*2+1][1] = r[3];
            }
            #pragma unroll
            for (int mt = 0; mt < 2; mt++)
                #pragma unroll
                for (int nt = 0; nt < 8; nt++) {
                    MMA_BF16(acc[mt][nt], ah[mt], bh[nt]);
                    MMA_BF16(acc[mt][nt], ah[mt], bl[nt]);
                    MMA_BF16(acc[mt][nt], al[mt], bh[nt]);
                }
        }
        __syncthreads();
    }

    // ---------------- epilogue ----------------
    const int groupID = lane >> 2, tig = lane & 3;
    #pragma unroll
    for (int mt = 0; mt < 2; mt++)
        #pragma unroll
        for (int nt = 0; nt < 8; nt++) {
            float* a = acc[mt][nt];
            const int row = bm0 + warpM * 32 + mt * 16 + groupID;
            const int col = bn0 + warpN * 64 + nt * 8 + tig * 2;
            if (OUTMODE == 0) {
                float* cp = Cf + (long)bz * sCb;
                *(float2*)(cp + (long)row * ldC + col) =
                    make_float2(a[0] * alpha, a[1] * alpha);
                *(float2*)(cp + (long)(row + 8) * ldC + col) =
                    make_float2(a[2] * alpha, a[3] * alpha);
            } else {
                // vT split: [b][n][tok] bf16 hi/lo
                const int b2 = row >> 11, tok = row & 2047;
                long base = (long)b2 * D_ * LS_ + tok;
                #pragma unroll
                for (int e = 0; e < 4; e++) {
                    float v = a[e];
                    long off = base + (long)(col + (e & 1)) * LS_ + ((e >> 1) << 3);
                    bf16 h = __float2bfloat16(v);
                    Ch[off] = h;
                    Cl[off] = __float2bfloat16(v - __bfloat162float(h));
                }
            }
        }
}

// ======================= convert / pointwise ===============================
template<bool GATHER>
__global__ void __launch_bounds__(256)
split_kernel(const float* __restrict__ src, bf16* __restrict__ h,
             bf16* __restrict__ l, int rows)
{
    long idx = (long)blockIdx.x * 256 + threadIdx.x;   // float4 index
    if (idx >= (long)rows * (D_ / 4)) return;
    int r = (int)(idx / (D_ / 4));
    int c = (int)(idx % (D_ / 4)) * 4;
    long sr;
    if (GATHER) {
        int s = r & 2047;
        sr = (long)(r >> 11) * L_ + ((s >> 9) << 11) + ((s & 511) << 2);
    } else sr = r;
    float4 v = *(const float4*)(src + sr * (long)D_ + c);
    uint2 hv, lv;
    split4(v, hv, lv);
    *(uint2*)(h + (long)r * D_ + c) = hv;
    *(uint2*)(l + (long)r * D_ + c) = lv;
}

__device__ __forceinline__ float block_sum(float v) {
    __shared__ float sh[8];
    int lane = threadIdx.x & 31, w = threadIdx.x >> 5;
    #pragma unroll
    for (int o = 16; o > 0; o >>= 1) v += __shfl_xor_sync(0xffffffffu, v, o);
    __syncthreads();
    if (lane == 0) sh[w] = v;
    __syncthreads();
    float t = 0.f;
    #pragma unroll
    for (int i = 0; i < 8; i++) t += sh[i];
    return t;
}
__device__ __forceinline__ float block_max(float v) {
    __shared__ float sh[8];
    int lane = threadIdx.x & 31, w = threadIdx.x >> 5;
    #pragma unroll
    for (int o = 16; o > 0; o >>= 1) v = fmaxf(v, __shfl_xor_sync(0xffffffffu, v, o));
    __syncthreads();
    if (lane == 0) sh[w] = v;
    __syncthreads();
    float t = -3.4e38f;
    #pragma unroll
    for (int i = 0; i < 8; i++) t = fmaxf(t, sh[i]);
    return t;
}

// LayerNorm -> bf16 hi/lo planes
__global__ void __launch_bounds__(256)
ln_split_kernel(const float* __restrict__ x, const float* __restrict__ gamma,
                const float* __restrict__ beta, bf16* __restrict__ xh,
                bf16* __restrict__ xl)
{
    const float* p = x + (long)blockIdx.x * D_;
    long ob = (long)blockIdx.x * D_;
    int t = threadIdx.x;
    float v0 = p[t], v1 = p[t + 256], v2 = p[t + 512];
    float mean = block_sum(v0 + v1 + v2) * (1.0f / D_);
    float d0 = v0 - mean, d1 = v1 - mean, d2 = v2 - mean;
    float var = block_sum(d0 * d0 + d1 * d1 + d2 * d2) * (1.0f / D_);
    float rstd = rsqrtf(var + 1e-5f);
    float y0 = d0 * rstd * gamma[t]       + beta[t];
    float y1 = d1 * rstd * gamma[t + 256] + beta[t + 256];
    float y2 = d2 * rstd * gamma[t + 512] + beta[t + 512];
    bf16 h0 = __float2bfloat16(y0), h1 = __float2bfloat16(y1), h2 = __float2bfloat16(y2);
    xh[ob + t]       = h0; xl[ob + t]       = __float2bfloat16(y0 - __bfloat162float(h0));
    xh[ob + t + 256] = h1; xl[ob + t + 256] = __float2bfloat16(y1 - __bfloat162float(h1));
    xh[ob + t + 512] = h2; xl[ob + t + 512] = __float2bfloat16(y2 - __bfloat162float(h2));
}

// row softmax (2048) -> bf16 hi/lo planes
__global__ void __launch_bounds__(256)
softmax2048_split(const float* __restrict__ S, bf16* __restrict__ Ph,
                  bf16* __restrict__ Pl)
{
    const float* p = S + (long)blockIdx.x * LS_;
    long ob = (long)blockIdx.x * LS_;
    int t = threadIdx.x;
    float v[8];
    float m = -3.4e38f;
    #pragma unroll
    for (int i = 0; i < 8; i++) { v[i] = p[t + i * 256]; m = fmaxf(m, v[i]); }
    m = block_max(m);
    float s = 0.f;
    #pragma unroll
    for (int i = 0; i < 8; i++) { v[i] = __expf(v[i] - m); s += v[i]; }
    s = block_sum(s);
    float inv = 1.0f / s;
    #pragma unroll
    for (int i = 0; i < 8; i++) {
        float y = v[i] * inv;
        bf16 h = __float2bfloat16(y);
        Ph[ob + t + i * 256] = h;
        Pl[ob + t + i * 256] = __float2bfloat16(y - __bfloat162float(h));
    }
}

__global__ void __launch_bounds__(256)
softmax768_kernel(const float* __restrict__ O, float* __restrict__ out)
{
    const float* p = O   + (long)blockIdx.x * D_;
    float*       q = out + (long)blockIdx.x * D_;
    int t = threadIdx.x;
    float v0 = p[t], v1 = p[t + 256], v2 = p[t + 512];
    float m = block_max(fmaxf(v0, fmaxf(v1, v2)));
    v0 = __expf(v0 - m); v1 = __expf(v1 - m); v2 = __expf(v2 - m);
    float inv = 1.0f / block_sum(v0 + v1 + v2);
    q[t] = v0 * inv; q[t + 256] = v1 * inv; q[t + 512] = v2 * inv;
}

// ======================= launch ===========================================
#define SYM(p, s) cudaGetSymbolAddress((void**)&p, s)

extern "C" void kernel_launch(void* const* d_in, const int* in_sizes, int n_in,
                              void* d_out, int out_size)
{
    const float* Q     = (const float*)d_in[0];
    const float* K     = (const float*)d_in[1];
    const float* V     = (const float*)d_in[2];
    const float* Wq    = (const float*)d_in[3];
    const float* Wk    = (const float*)d_in[4];
    const float* Wv    = (const float*)d_in[5];
    const float* gamma = (const float*)d_in[6];
    const float* beta  = (const float*)d_in[7];
    float* out = (float*)d_out;

    bf16 *xqh,*xql,*xkh,*xkl,*xvh,*xvl, *wqh,*wql,*wkh,*wkl,*wvh,*wvl;
    bf16 *vth,*vtl, *ph,*pl;
    float *gq,*gk,*gs;
    SYM(xqh,g_xqh); SYM(xql,g_xql); SYM(xkh,g_xkh); SYM(xkl,g_xkl);
    SYM(xvh,g_xvh); SYM(xvl,g_xvl);
    SYM(wqh,g_wqh); SYM(wql,g_wql); SYM(wkh,g_wkh); SYM(wkl,g_wkl);
    SYM(wvh,g_wvh); SYM(wvl,g_wvl);
    SYM(vth,g_vth); SYM(vtl,g_vtl); SYM(ph,g_ph); SYM(pl,g_pl);
    SYM(gq,g_q); SYM(gk,g_k); SYM(gs,g_s);

    // phase-disjoint aliases
    bf16 *qh = xqh, *ql = xql, *kh = xkh, *kl = xkl;  // LN output reuses input planes
    float *go = gq;                                    // O reuses q-projection buffer

    cudaFuncSetAttribute(bf_gemm<0>, cudaFuncAttributeMaxDynamicSharedMemorySize, SMEMSZ);
    cudaFuncSetAttribute(bf_gemm<1>, cudaFuncAttributeMaxDynamicSharedMemorySize, SMEMSZ);

    const dim3 blk(256);
    const float scale = 1.0f / sqrtf((float)D_);
    const int gX = (MTOT * (D_ / 4) + 255) / 256;
    const int gW = (D_ * (D_ / 4) + 255) / 256;

    // 0. gather+split inputs; split weights
    split_kernel<true ><<<gX, blk>>>(Q,  xqh, xql, MTOT);
    split_kernel<true ><<<gX, blk>>>(K,  xkh, xkl, MTOT);
    split_kernel<true ><<<gX, blk>>>(V,  xvh, xvl, MTOT);
    split_kernel<false><<<gW, blk>>>(Wq, wqh, wql, D_);
    split_kernel<false><<<gW, blk>>>(Wk, wkh, wkl, D_);
    split_kernel<false><<<gW, blk>>>(Wv, wvh, wvl, D_);

    // 1. projections (M=8192, N=768, K=768)
    bf_gemm<0><<<dim3(D_ / BN, MTOT / BM, 1), blk, SMEMSZ>>>(
        xqh, xql, wqh, wql, gq, nullptr, nullptr, D_, 1.0f, 0, 0, 0, D_, D_, D_);
    bf_gemm<0><<<dim3(D_ / BN, MTOT / BM, 1), blk, SMEMSZ>>>(
        xkh, xkl, wkh, wkl, gk, nullptr, nullptr, D_, 1.0f, 0, 0, 0, D_, D_, D_);
    bf_gemm<1><<<dim3(D_ / BN, MTOT / BM, 1), blk, SMEMSZ>>>(
        xvh, xvl, wvh, wvl, nullptr, vth, vtl, D_, 1.0f, 0, 0, 0, D_, D_, 0);

    // 2. LN -> bf16 hi/lo (writes alias the x planes, which are now dead)
    ln_split_kernel<<<MTOT, blk>>>(gq, gamma, beta, qh, ql);
    ln_split_kernel<<<MTOT, blk>>>(gk, gamma, beta, kh, kl);

    // 3. S = q k^T * scale (per batch)
    bf_gemm<0><<<dim3(LS_ / BN, LS_ / BM, B_), blk, SMEMSZ>>>(
        qh, ql, kh, kl, gs, nullptr, nullptr, D_, scale,
        (long)LS_ * D_, (long)LS_ * D_, (long)LS_ * LS_, D_, D_, LS_);

    // 4. row softmax -> P hi/lo
    softmax2048_split<<<B_ * LS_, blk>>>(gs, ph, pl);

    // 5. O = P v  (A = P [q,k], B = vT [n,k], K=2048); go aliases gq (q dead)
    bf_gemm<0><<<dim3(D_ / BN, LS_ / BM, B_), blk, SMEMSZ>>>(
        ph, pl, vth, vtl, go, nullptr, nullptr, LS_, 1.0f,
        (long)LS_ * LS_, (long)D_ * LS_, (long)LS_ * D_, LS_, LS_, D_);

    // 6. feature softmax -> out
    softmax768_kernel<<<MTOT, blk>>>(go, out);
}

// round 11
// speedup vs baseline: 1.1318x; 1.1318x over previous
#include <cuda_runtime.h>
#include <cuda_bf16.h>
#include <math.h>
#include <stdint.h>

// ---------------------------------------------------------------------------
// DilatedAttention via mma.sync bf16 (3-pass error-compensated split).
// Round-7-proven GEMM skeleton (double buffer, LDG->regs->STS, 1 sync/iter,
// 80KB smem => 2 CTA/SM) + round-9 precomputed bf16 hi/lo operand planes
// (no conversion ALU in the GEMM mainloop).
//   B=4, L=8192, D=768, SEG=2048, RATE=4 -> Ls=2048/batch, MTOT=8192
// ---------------------------------------------------------------------------

#define B_      4
#define L_      8192
#define D_      768
#define LS_     2048
#define MTOT    (B_ * LS_)

typedef __nv_bfloat16 bf16;

// ---------------- device scratch (allocation-free rule) --------------------
__device__ bf16  g_xqh[(long)MTOT * D_], g_xql[(long)MTOT * D_];
__device__ bf16  g_xkh[(long)MTOT * D_], g_xkl[(long)MTOT * D_];
__device__ bf16  g_xvh[(long)MTOT * D_], g_xvl[(long)MTOT * D_];
__device__ bf16  g_wqh[(long)D_ * D_],   g_wql[(long)D_ * D_];
__device__ bf16  g_wkh[(long)D_ * D_],   g_wkl[(long)D_ * D_];
__device__ bf16  g_wvh[(long)D_ * D_],   g_wvl[(long)D_ * D_];
__device__ float g_q[(long)MTOT * D_];          // q proj, later reused for O
__device__ float g_k[(long)MTOT * D_];
__device__ bf16  g_vth[(long)B_ * D_ * LS_], g_vtl[(long)B_ * D_ * LS_];
__device__ float g_s[(long)B_ * LS_ * LS_];     // 64 MB scores
__device__ bf16  g_ph[(long)B_ * LS_ * LS_], g_pl[(long)B_ * LS_ * LS_];

// ---------------- smem geometry -------------------------------------------
#define BM      128
#define BN      128
#define BKF     32                   // K per stage (elements)
#define ROWB    80                   // 64B data + 16B pad (LDSM conflict-free)
#define PLANE   (128 * ROWB)         // 10240 B
#define STAGE_B (4 * PLANE)          // Ah, Al, Bh, Bl = 40960 B
#define SMEMSZ  (2 * STAGE_B)        // double buffered = 81920 B (2 CTA/SM)

__device__ __forceinline__ uint32_t smem_u32(const void* p) {
    uint32_t a;
    asm("{ .reg .u64 t; cvta.to.shared.u64 t, %1; cvt.u32.u64 %0, t; }" : "=r"(a) : "l"(p));
    return a;
}

#define LDSM4(r, addr) \
    asm volatile("ldmatrix.sync.aligned.m8n8.x4.shared.b16 {%0,%1,%2,%3}, [%4];" \
        : "=r"((r)[0]), "=r"((r)[1]), "=r"((r)[2]), "=r"((r)[3]) : "r"(addr))

#define MMA_BF16(d, a, b) \
    asm volatile("mma.sync.aligned.m16n8k16.row.col.f32.bf16.bf16.f32 " \
        "{%0,%1,%2,%3}, {%4,%5,%6,%7}, {%8,%9}, {%0,%1,%2,%3};" \
        : "+f"((d)[0]), "+f"((d)[1]), "+f"((d)[2]), "+f"((d)[3]) \
        : "r"((a)[0]), "r"((a)[1]), "r"((a)[2]), "r"((a)[3]), "r"((b)[0]), "r"((b)[1]))

__device__ __forceinline__ void split4(float4 v, uint2& hv, uint2& lv) {
    __nv_bfloat162 h01 = __floats2bfloat162_rn(v.x, v.y);
    __nv_bfloat162 h23 = __floats2bfloat162_rn(v.z, v.w);
    float lx = v.x - __bfloat162float(h01.x);
    float ly = v.y - __bfloat162float(h01.y);
    float lz = v.z - __bfloat162float(h23.x);
    float lw = v.w - __bfloat162float(h23.y);
    __nv_bfloat162 l01 = __floats2bfloat162_rn(lx, ly);
    __nv_bfloat162 l23 = __floats2bfloat162_rn(lz, lw);
    hv.x = *(uint32_t*)&h01; hv.y = *(uint32_t*)&h23;
    lv.x = *(uint32_t*)&l01; lv.y = *(uint32_t*)&l23;
}

// ---------------- gmem -> regs: 8 x 16B per thread (4 planes x 2) ----------
// chunk w = tid + j*256 (j=0,1): r = w>>2 (row 0..127), ck = w&3 (16B col)
__device__ __forceinline__ void ldg_planes(
    const bf16* __restrict__ Ph, const bf16* __restrict__ Pl,
    int ld, int row0, int k0, int tid, uint4* rh, uint4* rl)
{
    #pragma unroll
    for (int j = 0; j < 2; j++) {
        int w = tid + (j << 8);
        int r = w >> 2;
        int ck = w & 3;
        long off = (long)(row0 + r) * ld + k0 + ck * 8;
        rh[j] = *(const uint4*)(Ph + off);
        rl[j] = *(const uint4*)(Pl + off);
    }
}

__device__ __forceinline__ void sts_planes(
    const uint4* rh, const uint4* rl, char* hiP, char* loP, int tid)
{
    #pragma unroll
    for (int j = 0; j < 2; j++) {
        int w = tid + (j << 8);
        int r = w >> 2;
        int ck = w & 3;
        uint32_t off = (uint32_t)(r * ROWB + ck * 16);
        *(uint4*)(hiP + off) = rh[j];
        *(uint4*)(loP + off) = rl[j];
    }
}

// ---------------- GEMM: C[128x128] = A[128xK] * B[128xK]^T (bf16 3-pass) ---
// OUTMODE 0: fp32 row-major C.  OUTMODE 1: vT split bf16 (Ch/Cl, per batch).
template<int OUTMODE>
__global__ void __launch_bounds__(256)
bf_gemm(const bf16* __restrict__ Ah, const bf16* __restrict__ Al,
        const bf16* __restrict__ Bh, const bf16* __restrict__ Bl,
        float* __restrict__ Cf, bf16* __restrict__ Ch, bf16* __restrict__ Cl,
        int K, float alpha, long sAb, long sBb, long sCb,
        int ldA, int ldB, int ldC)
{
    extern __shared__ char sm[];
    const uint32_t smem_base = smem_u32(sm);
    const int tid  = threadIdx.x;
    const int wid  = tid >> 5;
    const int lane = tid & 31;
    const int warpM = wid & 3;
    const int warpN = wid >> 2;
    const int bz = blockIdx.z;

    Ah += (long)bz * sAb;  Al += (long)bz * sAb;
    Bh += (long)bz * sBb;  Bl += (long)bz * sBb;

    const int bm0 = blockIdx.y * BM;
    const int bn0 = blockIdx.x * BN;
    const int NC  = K / BKF;

    float acc[2][8][4] = {};
    uint4 rAh[2], rAl[2], rBh[2], rBl[2];

    // prologue: fill buffer 0
    ldg_planes(Ah, Al, ldA, bm0, 0, tid, rAh, rAl);
    ldg_planes(Bh, Bl, ldB, bn0, 0, tid, rBh, rBl);
    sts_planes(rAh, rAl, sm,             sm + PLANE,     tid);
    sts_planes(rBh, rBl, sm + 2 * PLANE, sm + 3 * PLANE, tid);
    __syncthreads();

    const int aRow = warpM * 32 + (lane & 15);
    const int aKof = (lane >> 4) << 3;
    const int bRow = warpN * 64 + ((lane >> 4) << 3) + (lane & 7);
    const int bKof = ((lane >> 3) & 1) << 3;

    for (int c = 0; c < NC; c++) {
        const int buf = c & 1;
        if (c + 1 < NC) {
            ldg_planes(Ah, Al, ldA, bm0, (c + 1) * BKF, tid, rAh, rAl);
            ldg_planes(Bh, Bl, ldB, bn0, (c + 1) * BKF, tid, rBh, rBl);
        }

        const uint32_t sb  = smem_base + buf * STAGE_B;
        const uint32_t aHi = sb, aLo = sb + PLANE;
        const uint32_t bHi = sb + 2 * PLANE, bLo = sb + 3 * PLANE;

        #pragma unroll
        for (int k16 = 0; k16 < 2; k16++) {
            const int kk = k16 << 4;
            uint32_t ah[2][4], al[2][4], bh[8][2], bl[8][2];
            #pragma unroll
            for (int mt = 0; mt < 2; mt++) {
                uint32_t off = (uint32_t)((aRow + mt * 16) * ROWB + (kk + aKof) * 2);
                LDSM4(ah[mt], aHi + off);
                LDSM4(al[mt], aLo + off);
            }
            #pragma unroll
            for (int np = 0; np < 4; np++) {
                uint32_t off = (uint32_t)((bRow + np * 16) * ROWB + (kk + bKof) * 2);
                uint32_t r[4];
                LDSM4(r, bHi + off);
                bh[np*2][0] = r[0]; bh[np*2][1] = r[1];
                bh[np*2+1][0] = r[2]; bh[np*2+1][1] = r[3];
                LDSM4(r, bLo + off);
                bl[np*2][0] = r[0]; bl[np*2][1] = r[1];
                bl[np*2+1][0] = r[2]; bl[np*2+1][1] = r[3];
            }
            #pragma unroll
            for (int mt = 0; mt < 2; mt++)
                #pragma unroll
                for (int nt = 0; nt < 8; nt++) {
                    MMA_BF16(acc[mt][nt], ah[mt], bh[nt]);
                    MMA_BF16(acc[mt][nt], ah[mt], bl[nt]);
                    MMA_BF16(acc[mt][nt], al[mt], bh[nt]);
                }
        }

        if (c + 1 < NC) {
            char* nb = sm + (buf ^ 1) * STAGE_B;
            sts_planes(rAh, rAl, nb,             nb + PLANE,     tid);
            sts_planes(rBh, rBl, nb + 2 * PLANE, nb + 3 * PLANE, tid);
        }
        __syncthreads();
    }

    // ---------------- epilogue ----------------
    const int groupID = lane >> 2, tig = lane & 3;
    #pragma unroll
    for (int mt = 0; mt < 2; mt++)
        #pragma unroll
        for (int nt = 0; nt < 8; nt++) {
            float* a = acc[mt][nt];
            const int row = bm0 + warpM * 32 + mt * 16 + groupID;
            const int col = bn0 + warpN * 64 + nt * 8 + tig * 2;
            if (OUTMODE == 0) {
                float* cp = Cf + (long)bz * sCb;
                *(float2*)(cp + (long)row * ldC + col) =
                    make_float2(a[0] * alpha, a[1] * alpha);
                *(float2*)(cp + (long)(row + 8) * ldC + col) =
                    make_float2(a[2] * alpha, a[3] * alpha);
            } else {
                // vT split: [b][n][tok] bf16 hi/lo
                const int b2 = row >> 11, tok = row & 2047;
                long base = (long)b2 * D_ * LS_ + tok;
                #pragma unroll
                for (int e = 0; e < 4; e++) {
                    float v = a[e];
                    long off = base + (long)(col + (e & 1)) * LS_ + ((e >> 1) << 3);
                    bf16 h = __float2bfloat16(v);
                    Ch[off] = h;
                    Cl[off] = __float2bfloat16(v - __bfloat162float(h));
                }
            }
        }
}

// ======================= convert / pointwise ===============================
template<bool GATHER>
__global__ void __launch_bounds__(256)
split_kernel(const float* __restrict__ src, bf16* __restrict__ h,
             bf16* __restrict__ l, int rows)
{
    long idx = (long)blockIdx.x * 256 + threadIdx.x;   // float4 index
    if (idx >= (long)rows * (D_ / 4)) return;
    int r = (int)(idx / (D_ / 4));
    int c = (int)(idx % (D_ / 4)) * 4;
    long sr;
    if (GATHER) {
        int s = r & 2047;
        sr = (long)(r >> 11) * L_ + ((s >> 9) << 11) + ((s & 511) << 2);
    } else sr = r;
    float4 v = *(const float4*)(src + sr * (long)D_ + c);
    uint2 hv, lv;
    split4(v, hv, lv);
    *(uint2*)(h + (long)r * D_ + c) = hv;
    *(uint2*)(l + (long)r * D_ + c) = lv;
}

__device__ __forceinline__ float block_sum(float v) {
    __shared__ float sh[8];
    int lane = threadIdx.x & 31, w = threadIdx.x >> 5;
    #pragma unroll
    for (int o = 16; o > 0; o >>= 1) v += __shfl_xor_sync(0xffffffffu, v, o);
    __syncthreads();
    if (lane == 0) sh[w] = v;
    __syncthreads();
    float t = 0.f;
    #pragma unroll
    for (int i = 0; i < 8; i++) t += sh[i];
    return t;
}
__device__ __forceinline__ float block_max(float v) {
    __shared__ float sh[8];
    int lane = threadIdx.x & 31, w = threadIdx.x >> 5;
    #pragma unroll
    for (int o = 16; o > 0; o >>= 1) v = fmaxf(v, __shfl_xor_sync(0xffffffffu, v, o));
    __syncthreads();
    if (lane == 0) sh[w] = v;
    __syncthreads();
    float t = -3.4e38f;
    #pragma unroll
    for (int i = 0; i < 8; i++) t = fmaxf(t, sh[i]);
    return t;
}

// LayerNorm -> bf16 hi/lo planes
__global__ void __launch_bounds__(256)
ln_split_kernel(const float* __restrict__ x, const float* __restrict__ gamma,
                const float* __restrict__ beta, bf16* __restrict__ xh,
                bf16* __restrict__ xl)
{
    const float* p = x + (long)blockIdx.x * D_;
    long ob = (long)blockIdx.x * D_;
    int t = threadIdx.x;
    float v0 = p[t], v1 = p[t + 256], v2 = p[t + 512];
    float mean = block_sum(v0 + v1 + v2) * (1.0f / D_);
    float d0 = v0 - mean, d1 = v1 - mean, d2 = v2 - mean;
    float var = block_sum(d0 * d0 + d1 * d1 + d2 * d2) * (1.0f / D_);
    float rstd = rsqrtf(var + 1e-5f);
    float y0 = d0 * rstd * gamma[t]       + beta[t];
    float y1 = d1 * rstd * gamma[t + 256] + beta[t + 256];
    float y2 = d2 * rstd * gamma[t + 512] + beta[t + 512];
    bf16 h0 = __float2bfloat16(y0), h1 = __float2bfloat16(y1), h2 = __float2bfloat16(y2);
    xh[ob + t]       = h0; xl[ob + t]       = __float2bfloat16(y0 - __bfloat162float(h0));
    xh[ob + t + 256] = h1; xl[ob + t + 256] = __float2bfloat16(y1 - __bfloat162float(h1));
    xh[ob + t + 512] = h2; xl[ob + t + 512] = __float2bfloat16(y2 - __bfloat162float(h2));
}

// row softmax (2048) -> bf16 hi/lo planes
__global__ void __launch_bounds__(256)
softmax2048_split(const float* __restrict__ S, bf16* __restrict__ Ph,
                  bf16* __restrict__ Pl)
{
    const float* p = S + (long)blockIdx.x * LS_;
    long ob = (long)blockIdx.x * LS_;
    int t = threadIdx.x;
    float v[8];
    float m = -3.4e38f;
    #pragma unroll
    for (int i = 0; i < 8; i++) { v[i] = p[t + i * 256]; m = fmaxf(m, v[i]); }
    m = block_max(m);
    float s = 0.f;
    #pragma unroll
    for (int i = 0; i < 8; i++) { v[i] = __expf(v[i] - m); s += v[i]; }
    s = block_sum(s);
    float inv = 1.0f / s;
    #pragma unroll
    for (int i = 0; i < 8; i++) {
        float y = v[i] * inv;
        bf16 h = __float2bfloat16(y);
        Ph[ob + t + i * 256] = h;
        Pl[ob + t + i * 256] = __float2bfloat16(y - __bfloat162float(h));
    }
}

__global__ void __launch_bounds__(256)
softmax768_kernel(const float* __restrict__ O, float* __restrict__ out)
{
    const float* p = O   + (long)blockIdx.x * D_;
    float*       q = out + (long)blockIdx.x * D_;
    int t = threadIdx.x;
    float v0 = p[t], v1 = p[t + 256], v2 = p[t + 512];
    float m = block_max(fmaxf(v0, fmaxf(v1, v2)));
    v0 = __expf(v0 - m); v1 = __expf(v1 - m); v2 = __expf(v2 - m);
    float inv = 1.0f / block_sum(v0 + v1 + v2);
    q[t] = v0 * inv; q[t + 256] = v1 * inv; q[t + 512] = v2 * inv;
}

// ======================= launch ===========================================
#define SYM(p, s) cudaGetSymbolAddress((void**)&p, s)

extern "C" void kernel_launch(void* const* d_in, const int* in_sizes, int n_in,
                              void* d_out, int out_size)
{
    const float* Q     = (const float*)d_in[0];
    const float* K     = (const float*)d_in[1];
    const float* V     = (const float*)d_in[2];
    const float* Wq    = (const float*)d_in[3];
    const float* Wk    = (const float*)d_in[4];
    const float* Wv    = (const float*)d_in[5];
    const float* gamma = (const float*)d_in[6];
    const float* beta  = (const float*)d_in[7];
    float* out = (float*)d_out;

    bf16 *xqh,*xql,*xkh,*xkl,*xvh,*xvl, *wqh,*wql,*wkh,*wkl,*wvh,*wvl;
    bf16 *vth,*vtl, *ph,*pl;
    float *gq,*gk,*gs;
    SYM(xqh,g_xqh); SYM(xql,g_xql); SYM(xkh,g_xkh); SYM(xkl,g_xkl);
    SYM(xvh,g_xvh); SYM(xvl,g_xvl);
    SYM(wqh,g_wqh); SYM(wql,g_wql); SYM(wkh,g_wkh); SYM(wkl,g_wkl);
    SYM(wvh,g_wvh); SYM(wvl,g_wvl);
    SYM(vth,g_vth); SYM(vtl,g_vtl); SYM(ph,g_ph); SYM(pl,g_pl);
    SYM(gq,g_q); SYM(gk,g_k); SYM(gs,g_s);

    // phase-disjoint aliases
    bf16 *qh = xqh, *ql = xql, *kh = xkh, *kl = xkl;  // LN output reuses input planes
    float *go = gq;                                    // O reuses q-projection buffer

    cudaFuncSetAttribute(bf_gemm<0>, cudaFuncAttributeMaxDynamicSharedMemorySize, SMEMSZ);
    cudaFuncSetAttribute(bf_gemm<1>, cudaFuncAttributeMaxDynamicSharedMemorySize, SMEMSZ);

    const dim3 blk(256);
    const float scale = 1.0f / sqrtf((float)D_);
    const int gX = (MTOT * (D_ / 4) + 255) / 256;
    const int gW = (D_ * (D_ / 4) + 255) / 256;

    // 0. gather+split inputs; split weights
    split_kernel<true ><<<gX, blk>>>(Q,  xqh, xql, MTOT);
    split_kernel<true ><<<gX, blk>>>(K,  xkh, xkl, MTOT);
    split_kernel<true ><<<gX, blk>>>(V,  xvh, xvl, MTOT);
    split_kernel<false><<<gW, blk>>>(Wq, wqh, wql, D_);
    split_kernel<false><<<gW, blk>>>(Wk, wkh, wkl, D_);
    split_kernel<false><<<gW, blk>>>(Wv, wvh, wvl, D_);

    // 1. projections (M=8192, N=768, K=768)
    bf_gemm<0><<<dim3(D_ / BN, MTOT / BM, 1), blk, SMEMSZ>>>(
        xqh, xql, wqh, wql, gq, nullptr, nullptr, D_, 1.0f, 0, 0, 0, D_, D_, D_);
    bf_gemm<0><<<dim3(D_ / BN, MTOT / BM, 1), blk, SMEMSZ>>>(
        xkh, xkl, wkh, wkl, gk, nullptr, nullptr, D_, 1.0f, 0, 0, 0, D_, D_, D_);
    bf_gemm<1><<<dim3(D_ / BN, MTOT / BM, 1), blk, SMEMSZ>>>(
        xvh, xvl, wvh, wvl, nullptr, vth, vtl, D_, 1.0f, 0, 0, 0, D_, D_, 0);

    // 2. LN -> bf16 hi/lo (writes alias the x planes, which are now dead)
    ln_split_kernel<<<MTOT, blk>>>(gq, gamma, beta, qh, ql);
    ln_split_kernel<<<MTOT, blk>>>(gk, gamma, beta, kh, kl);

    // 3. S = q k^T * scale (per batch)
    bf_gemm<0><<<dim3(LS_ / BN, LS_ / BM, B_), blk, SMEMSZ>>>(
        qh, ql, kh, kl, gs, nullptr, nullptr, D_, scale,
        (long)LS_ * D_, (long)LS_ * D_, (long)LS_ * LS_, D_, D_, LS_);

    // 4. row softmax -> P hi/lo
    softmax2048_split<<<B_ * LS_, blk>>>(gs, ph, pl);

    // 5. O = P v  (A = P [q,k], B = vT [n,k], K=2048); go aliases gq (q dead)
    bf_gemm<0><<<dim3(D_ / BN, LS_ / BM, B_), blk, SMEMSZ>>>(
        ph, pl, vth, vtl, go, nullptr, nullptr, LS_, 1.0f,
        (long)LS_ * LS_, (long)D_ * LS_, (long)LS_ * D_, LS_, LS_, D_);

    // 6. feature softmax -> out
    softmax768_kernel<<<MTOT, blk>>>(go, out);
}

// round 13
// speedup vs baseline: 1.5136x; 1.3373x over previous
#include <cuda_runtime.h>
#include <cuda_fp16.h>
#include <math.h>
#include <stdint.h>

// ---------------------------------------------------------------------------
// DilatedAttention via mma.sync fp16 2-pass error-compensated GEMMs.
//   x = h + l (fp16 split); x*y ~= h*h' + h*l'  (dropped l*y ~ 2^-12 rel)
// Round-7-proven skeleton: fused in-mainloop split, double buffer, 80->61KB
// smem, one __syncthreads per K-chunk. A needs hi plane only; B hi+lo.
//   B=4, L=8192, D=768, SEG=2048, RATE=4 -> Ls=2048/batch, MTOT=8192
// ---------------------------------------------------------------------------

#define B_      4
#define L_      8192
#define D_      768
#define LS_     2048
#define MTOT    (B_ * LS_)

// scratch (allocation-free rule: __device__ globals)
__device__ float g_q[(long)MTOT * D_];
__device__ float g_k[(long)MTOT * D_];
__device__ float g_vT[(long)B_ * D_ * LS_];   // projected V, transposed per batch
__device__ float g_s[(long)B_ * LS_ * LS_];   // 64 MB scores
__device__ float g_o[(long)MTOT * D_];

// ---------------- smem geometry -------------------------------------------
#define BM      128
#define BN      128
#define BKF     32                   // K per tile chunk (elements)
#define ROWB    80                   // 64B data + 16B pad (LDSM conflict-free)
#define PLANE   (128 * ROWB)         // 10240 B
#define STAGE_B (3 * PLANE)          // A_hi, B_hi, B_lo = 30720 B
#define SMEMSZ  (2 * STAGE_B)        // double buffered = 61440 B

__device__ __forceinline__ uint32_t smem_u32(const void* p) {
    uint32_t a;
    asm("{ .reg .u64 t; cvta.to.shared.u64 t, %1; cvt.u32.u64 %0, t; }" : "=r"(a) : "l"(p));
    return a;
}

#define LDSM4(r, addr) \
    asm volatile("ldmatrix.sync.aligned.m8n8.x4.shared.b16 {%0,%1,%2,%3}, [%4];" \
        : "=r"((r)[0]), "=r"((r)[1]), "=r"((r)[2]), "=r"((r)[3]) : "r"(addr))

#define MMA_F16(d, a, b) \
    asm volatile("mma.sync.aligned.m16n8k16.row.col.f32.f16.f16.f32 " \
        "{%0,%1,%2,%3}, {%4,%5,%6,%7}, {%8,%9}, {%0,%1,%2,%3};" \
        : "+f"((d)[0]), "+f"((d)[1]), "+f"((d)[2]), "+f"((d)[3]) \
        : "r"((a)[0]), "r"((a)[1]), "r"((a)[2]), "r"((a)[3]), "r"((b)[0]), "r"((b)[1]))

// ---------------- gmem -> regs (fp32), 4 float4 per thread -----------------
template<bool GATHER>
__device__ __forceinline__ void ldg_tile(const float* __restrict__ src, int ld,
                                         int rowBase, int k0, int tid, float4* reg)
{
    #pragma unroll
    for (int i = 0; i < 4; i++) {
        int f = tid + (i << 8);          // 0..1023 float4 slots (128 rows x 8)
        int r = f >> 3;
        int c = (f & 7) << 2;
        int gm = rowBase + r;
        long sr;
        if (GATHER) {
            int s = gm & 2047;
            sr = (long)(gm >> 11) * L_ + ((s >> 9) << 11) + ((s & 511) << 2);
        } else {
            sr = gm;
        }
        reg[i] = *(const float4*)(src + sr * (long)ld + k0 + c);
    }
}

// ---------------- regs -> smem: A hi-only ----------------------------------
__device__ __forceinline__ void sts_A(const float4* reg, char* hiP, int tid)
{
    #pragma unroll
    for (int i = 0; i < 4; i++) {
        float4 v = reg[i];
        int f = tid + (i << 8);
        int r = f >> 3;
        int c = (f & 7) << 2;
        __half2 h01 = __floats2half2_rn(v.x, v.y);
        __half2 h23 = __floats2half2_rn(v.z, v.w);
        uint32_t off = (uint32_t)(r * ROWB + (c << 1));
        uint2 hv;
        hv.x = *(uint32_t*)&h01; hv.y = *(uint32_t*)&h23;
        *(uint2*)(hiP + off) = hv;
    }
}

// ---------------- regs -> smem: B hi + lo ----------------------------------
__device__ __forceinline__ void sts_B(const float4* reg, char* hiP, char* loP, int tid)
{
    #pragma unroll
    for (int i = 0; i < 4; i++) {
        float4 v = reg[i];
        int f = tid + (i << 8);
        int r = f >> 3;
        int c = (f & 7) << 2;
        __half2 h01 = __floats2half2_rn(v.x, v.y);
        __half2 h23 = __floats2half2_rn(v.z, v.w);
        float lx = v.x - __half2float(__low2half(h01));
        float ly = v.y - __half2float(__high2half(h01));
        float lz = v.z - __half2float(__low2half(h23));
        float lw = v.w - __half2float(__high2half(h23));
        __half2 l01 = __floats2half2_rn(lx, ly);
        __half2 l23 = __floats2half2_rn(lz, lw);
        uint32_t off = (uint32_t)(r * ROWB + (c << 1));
        uint2 hv, lv;
        hv.x = *(uint32_t*)&h01; hv.y = *(uint32_t*)&h23;
        lv.x = *(uint32_t*)&l01; lv.y = *(uint32_t*)&l23;
        *(uint2*)(hiP + off) = hv;
        *(uint2*)(loP + off) = lv;
    }
}

// ---------------- shared mainloop body -------------------------------------
struct Frag { float acc[2][8][4]; };

__device__ __forceinline__ void mma_chunk(uint32_t sb, int aRow, int aKof,
                                          int bRow, int bKof, Frag& fr)
{
    const uint32_t aHi = sb, bHi = sb + PLANE, bLo = sb + 2 * PLANE;
    #pragma unroll
    for (int k16 = 0; k16 < 2; k16++) {
        const int kk = k16 << 4;
        uint32_t ah[2][4], bh[8][2], bl[8][2];
        #pragma unroll
        for (int mt = 0; mt < 2; mt++) {
            uint32_t off = (uint32_t)((aRow + mt * 16) * ROWB + (kk + aKof) * 2);
            LDSM4(ah[mt], aHi + off);
        }
        #pragma unroll
        for (int np = 0; np < 4; np++) {
            uint32_t off = (uint32_t)((bRow + np * 16) * ROWB + (kk + bKof) * 2);
            uint32_t r[4];
            LDSM4(r, bHi + off);
            bh[np*2][0] = r[0]; bh[np*2][1] = r[1];
            bh[np*2+1][0] = r[2]; bh[np*2+1][1] = r[3];
            LDSM4(r, bLo + off);
            bl[np*2][0] = r[0]; bl[np*2][1] = r[1];
            bl[np*2+1][0] = r[2]; bl[np*2+1][1] = r[3];
        }
        #pragma unroll
        for (int mt = 0; mt < 2; mt++)
            #pragma unroll
            for (int nt = 0; nt < 8; nt++) {
                MMA_F16(fr.acc[mt][nt], ah[mt], bh[nt]);
                MMA_F16(fr.acc[mt][nt], ah[mt], bl[nt]);
            }
    }
}

// ---------------- generic GEMM (QK, PV): C = A B^T * alpha, fp32 out ------
__global__ void __launch_bounds__(256)
bf_gemm(const float* __restrict__ A, const float* __restrict__ Bm,
        float* __restrict__ C, int K, float alpha,
        long sAb, long sBb, long sCb, int ldA, int ldB, int ldC)
{
    extern __shared__ char sm[];
    const uint32_t smem_base = smem_u32(sm);
    const int tid  = threadIdx.x;
    const int wid  = tid >> 5;
    const int lane = tid & 31;
    const int warpM = wid & 3;
    const int warpN = wid >> 2;
    const int bz = blockIdx.z;

    A  += (long)bz * sAb;
    Bm += (long)bz * sBb;
    C  += (long)bz * sCb;

    const int bm0 = blockIdx.y * BM;
    const int bn0 = blockIdx.x * BN;
    const int NC  = K / BKF;

    Frag fr = {};
    float4 ra[4], rb[4];

    ldg_tile<false>(A,  ldA, bm0, 0, tid, ra);
    ldg_tile<false>(Bm, ldB, bn0, 0, tid, rb);
    sts_A(ra, sm, tid);
    sts_B(rb, sm + PLANE, sm + 2 * PLANE, tid);
    __syncthreads();

    const int aRow = warpM * 32 + (lane & 15);
    const int aKof = (lane >> 4) << 3;
    const int bRow = warpN * 64 + ((lane >> 4) << 3) + (lane & 7);
    const int bKof = ((lane >> 3) & 1) << 3;

    for (int c = 0; c < NC; c++) {
        const int buf = c & 1;
        if (c + 1 < NC) {
            ldg_tile<false>(A,  ldA, bm0, (c + 1) * BKF, tid, ra);
            ldg_tile<false>(Bm, ldB, bn0, (c + 1) * BKF, tid, rb);
        }
        mma_chunk(smem_base + buf * STAGE_B, aRow, aKof, bRow, bKof, fr);
        if (c + 1 < NC) {
            char* nb = sm + (buf ^ 1) * STAGE_B;
            sts_A(ra, nb, tid);
            sts_B(rb, nb + PLANE, nb + 2 * PLANE, tid);
        }
        __syncthreads();
    }

    const int groupID = lane >> 2, tig = lane & 3;
    #pragma unroll
    for (int mt = 0; mt < 2; mt++)
        #pragma unroll
        for (int nt = 0; nt < 8; nt++) {
            float* a = fr.acc[mt][nt];
            const int row = bm0 + warpM * 32 + mt * 16 + groupID;
            const int col = bn0 + warpN * 64 + nt * 8 + tig * 2;
            *(float2*)(C + (long)row * ldC + col) =
                make_float2(a[0] * alpha, a[1] * alpha);
            *(float2*)(C + (long)(row + 8) * ldC + col) =
                make_float2(a[2] * alpha, a[3] * alpha);
        }
}

// ---------------- merged projection GEMM (single launch, z selects) --------
struct ProjPtrs {
    const float *A0, *A1, *A2;
    const float *W0, *W1, *W2;
    float *Cq, *Ck, *vT;
};

__global__ void __launch_bounds__(256)
proj_gemm(ProjPtrs p)
{
    extern __shared__ char sm[];
    const uint32_t smem_base = smem_u32(sm);
    const int tid  = threadIdx.x;
    const int wid  = tid >> 5;
    const int lane = tid & 31;
    const int warpM = wid & 3;
    const int warpN = wid >> 2;
    const int z = blockIdx.z;

    const float* A  = (z == 0) ? p.A0 : (z == 1) ? p.A1 : p.A2;
    const float* Bm = (z == 0) ? p.W0 : (z == 1) ? p.W1 : p.W2;

    const int bm0 = blockIdx.y * BM;
    const int bn0 = blockIdx.x * BN;
    const int NC  = D_ / BKF;      // 24

    Frag fr = {};
    float4 ra[4], rb[4];

    ldg_tile<true >(A,  D_, bm0, 0, tid, ra);
    ldg_tile<false>(Bm, D_, bn0, 0, tid, rb);
    sts_A(ra, sm, tid);
    sts_B(rb, sm + PLANE, sm + 2 * PLANE, tid);
    __syncthreads();

    const int aRow = warpM * 32 + (lane & 15);
    const int aKof = (lane >> 4) << 3;
    const int bRow = warpN * 64 + ((lane >> 4) << 3) + (lane & 7);
    const int bKof = ((lane >> 3) & 1) << 3;

    for (int c = 0; c < NC; c++) {
        const int buf = c & 1;
        if (c + 1 < NC) {
            ldg_tile<true >(A,  D_, bm0, (c + 1) * BKF, tid, ra);
            ldg_tile<false>(Bm, D_, bn0, (c + 1) * BKF, tid, rb);
        }
        mma_chunk(smem_base + buf * STAGE_B, aRow, aKof, bRow, bKof, fr);
        if (c + 1 < NC) {
            char* nb = sm + (buf ^ 1) * STAGE_B;
            sts_A(ra, nb, tid);
            sts_B(rb, nb + PLANE, nb + 2 * PLANE, tid);
        }
        __syncthreads();
    }

    const int groupID = lane >> 2, tig = lane & 3;
    #pragma unroll
    for (int mt = 0; mt < 2; mt++)
        #pragma unroll
        for (int nt = 0; nt < 8; nt++) {
            float* a = fr.acc[mt][nt];
            const int row = bm0 + warpM * 32 + mt * 16 + groupID;
            const int col = bn0 + warpN * 64 + nt * 8 + tig * 2;
            if (z < 2) {
                float* C = z ? p.Ck : p.Cq;
                *(float2*)(C + (long)row * D_ + col) = make_float2(a[0], a[1]);
                *(float2*)(C + (long)(row + 8) * D_ + col) = make_float2(a[2], a[3]);
            } else {
                // vT: [b][n][tok]
                const int b2 = row >> 11, tok = row & 2047;
                long base = (long)b2 * D_ * LS_ + tok;
                #pragma unroll
                for (int e = 0; e < 4; e++) {
                    long off = base + (long)(col + (e & 1)) * LS_ + ((e >> 1) << 3);
                    p.vT[off] = a[e];
                }
            }
        }
}

// ======================= reductions / pointwise ============================
__device__ __forceinline__ float block_sum(float v) {
    __shared__ float sh[8];
    int lane = threadIdx.x & 31, w = threadIdx.x >> 5;
    #pragma unroll
    for (int o = 16; o > 0; o >>= 1) v += __shfl_xor_sync(0xffffffffu, v, o);
    __syncthreads();
    if (lane == 0) sh[w] = v;
    __syncthreads();
    float t = 0.f;
    #pragma unroll
    for (int i = 0; i < 8; i++) t += sh[i];
    return t;
}
__device__ __forceinline__ float block_max(float v) {
    __shared__ float sh[8];
    int lane = threadIdx.x & 31, w = threadIdx.x >> 5;
    #pragma unroll
    for (int o = 16; o > 0; o >>= 1) v = fmaxf(v, __shfl_xor_sync(0xffffffffu, v, o));
    __syncthreads();
    if (lane == 0) sh[w] = v;
    __syncthreads();
    float t = -3.4e38f;
    #pragma unroll
    for (int i = 0; i < 8; i++) t = fmaxf(t, sh[i]);
    return t;
}

// merged LayerNorm (in place) for q and k: blockIdx.y selects buffer
__global__ void __launch_bounds__(256)
ln_kernel(float* __restrict__ xq, float* __restrict__ xk,
          const float* __restrict__ gamma, const float* __restrict__ beta)
{
    float* x = blockIdx.y ? xk : xq;
    float* pp = x + (long)blockIdx.x * D_;
    int t = threadIdx.x;
    float v0 = pp[t], v1 = pp[t + 256], v2 = pp[t + 512];
    float mean = block_sum(v0 + v1 + v2) * (1.0f / D_);
    float d0 = v0 - mean, d1 = v1 - mean, d2 = v2 - mean;
    float var = block_sum(d0 * d0 + d1 * d1 + d2 * d2) * (1.0f / D_);
    float rstd = rsqrtf(var + 1e-5f);
    pp[t]       = d0 * rstd * gamma[t]       + beta[t];
    pp[t + 256] = d1 * rstd * gamma[t + 256] + beta[t + 256];
    pp[t + 512] = d2 * rstd * gamma[t + 512] + beta[t + 512];
}

__global__ void __launch_bounds__(256)
softmax2048_kernel(float* __restrict__ S)
{
    float* p = S + (long)blockIdx.x * LS_;
    int t = threadIdx.x;
    float v[8];
    float m = -3.4e38f;
    #pragma unroll
    for (int i = 0; i < 8; i++) { v[i] = p[t + i * 256]; m = fmaxf(m, v[i]); }
    m = block_max(m);
    float s = 0.f;
    #pragma unroll
    for (int i = 0; i < 8; i++) { v[i] = __expf(v[i] - m); s += v[i]; }
    s = block_sum(s);
    float inv = 1.0f / s;
    #pragma unroll
    for (int i = 0; i < 8; i++) p[t + i * 256] = v[i] * inv;
}

__global__ void __launch_bounds__(256)
softmax768_kernel(const float* __restrict__ O, float* __restrict__ out)
{
    const float* p = O   + (long)blockIdx.x * D_;
    float*       q = out + (long)blockIdx.x * D_;
    int t = threadIdx.x;
    float v0 = p[t], v1 = p[t + 256], v2 = p[t + 512];
    float m = block_max(fmaxf(v0, fmaxf(v1, v2)));
    v0 = __expf(v0 - m); v1 = __expf(v1 - m); v2 = __expf(v2 - m);
    float inv = 1.0f / block_sum(v0 + v1 + v2);
    q[t] = v0 * inv; q[t + 256] = v1 * inv; q[t + 512] = v2 * inv;
}

// ======================= launch ===========================================
extern "C" void kernel_launch(void* const* d_in, const int* in_sizes, int n_in,
                              void* d_out, int out_size)
{
    const float* Q     = (const float*)d_in[0];
    const float* K     = (const float*)d_in[1];
    const float* V     = (const float*)d_in[2];
    const float* Wq    = (const float*)d_in[3];
    const float* Wk    = (const float*)d_in[4];
    const float* Wv    = (const float*)d_in[5];
    const float* gamma = (const float*)d_in[6];
    const float* beta  = (const float*)d_in[7];
    float* out = (float*)d_out;

    float *gq, *gk, *gvT, *gs, *go;
    cudaGetSymbolAddress((void**)&gq,  g_q);
    cudaGetSymbolAddress((void**)&gk,  g_k);
    cudaGetSymbolAddress((void**)&gvT, g_vT);
    cudaGetSymbolAddress((void**)&gs,  g_s);
    cudaGetSymbolAddress((void**)&go,  g_o);

    cudaFuncSetAttribute(bf_gemm,   cudaFuncAttributeMaxDynamicSharedMemorySize, SMEMSZ);
    cudaFuncSetAttribute(proj_gemm, cudaFuncAttributeMaxDynamicSharedMemorySize, SMEMSZ);

    const dim3 blk(256);
    const float scale = 1.0f / sqrtf((float)D_);

    // 1. merged projections (one launch, z in {q,k,v}): C = gather(X) @ W^T
    ProjPtrs pp;
    pp.A0 = Q;  pp.A1 = K;  pp.A2 = V;
    pp.W0 = Wq; pp.W1 = Wk; pp.W2 = Wv;
    pp.Cq = gq; pp.Ck = gk; pp.vT = gvT;
    proj_gemm<<<dim3(D_ / BN, MTOT / BM, 3), blk, SMEMSZ>>>(pp);

    // 2. merged qk LayerNorm
    ln_kernel<<<dim3(MTOT, 2), blk>>>(gq, gk, gamma, beta);

    // 3. S = q k^T * scale (per batch, both K-major)
    bf_gemm<<<dim3(LS_ / BN, LS_ / BM, B_), blk, SMEMSZ>>>(
        gq, gk, gs, D_, scale,
        (long)LS_ * D_, (long)LS_ * D_, (long)LS_ * LS_, D_, D_, LS_);

    // 4. row softmax
    softmax2048_kernel<<<B_ * LS_, blk>>>(gs);

    // 5. O = P v  (B = vT, K-major rows of length 2048)
    bf_gemm<<<dim3(D_ / BN, LS_ / BM, B_), blk, SMEMSZ>>>(
        gs, gvT, go, LS_, 1.0f,
        (long)LS_ * LS_, (long)D_ * LS_, (long)LS_ * D_, LS_, LS_, D_);

    // 6. feature softmax -> out
    softmax768_kernel<<<MTOT, blk>>>(go, out);
}

// round 15
// speedup vs baseline: 1.7433x; 1.1517x over previous
#include <cuda_runtime.h>
#include <cuda_fp16.h>
#include <math.h>
#include <stdint.h>

// ---------------------------------------------------------------------------
// DilatedAttention via single-pass fp16 mma.sync GEMMs (fp32 accumulate).
// Calibration from R12: 2-pass fp16 measured rel_err 1.68e-5; single-pass
// drops one more 2^-11-scale term -> predicted ~3e-5, threshold 1e-3.
// Skeleton: fused in-mainloop cvt, double buffer, 40KB smem, 1 sync/chunk.
//   B=4, L=8192, D=768, SEG=2048, RATE=4 -> Ls=2048/batch, MTOT=8192
// ---------------------------------------------------------------------------

#define B_      4
#define L_      8192
#define D_      768
#define LS_     2048
#define MTOT    (B_ * LS_)

// scratch (allocation-free rule: __device__ globals)
__device__ float g_q[(long)MTOT * D_];
__device__ float g_k[(long)MTOT * D_];
__device__ float g_vT[(long)B_ * D_ * LS_];   // projected V, transposed per batch
__device__ float g_s[(long)B_ * LS_ * LS_];   // 64 MB scores
__device__ float g_o[(long)MTOT * D_];

// ---------------- smem geometry -------------------------------------------
#define BM      128
#define BN      128
#define BKF     32                   // K per tile chunk (elements)
#define ROWB    80                   // 64B data + 16B pad (LDSM conflict-free)
#define PLANE   (128 * ROWB)         // 10240 B
#define STAGE_B (2 * PLANE)          // A, B = 20480 B
#define SMEMSZ  (2 * STAGE_B)        // double buffered = 40960 B

__device__ __forceinline__ uint32_t smem_u32(const void* p) {
    uint32_t a;
    asm("{ .reg .u64 t; cvta.to.shared.u64 t, %1; cvt.u32.u64 %0, t; }" : "=r"(a) : "l"(p));
    return a;
}

#define LDSM4(r, addr) \
    asm volatile("ldmatrix.sync.aligned.m8n8.x4.shared.b16 {%0,%1,%2,%3}, [%4];" \
        : "=r"((r)[0]), "=r"((r)[1]), "=r"((r)[2]), "=r"((r)[3]) : "r"(addr))

#define MMA_F16(d, a, b) \
    asm volatile("mma.sync.aligned.m16n8k16.row.col.f32.f16.f16.f32 " \
        "{%0,%1,%2,%3}, {%4,%5,%6,%7}, {%8,%9}, {%0,%1,%2,%3};" \
        : "+f"((d)[0]), "+f"((d)[1]), "+f"((d)[2]), "+f"((d)[3]) \
        : "r"((a)[0]), "r"((a)[1]), "r"((a)[2]), "r"((a)[3]), "r"((b)[0]), "r"((b)[1]))

// ---------------- gmem -> regs (fp32), 4 float4 per thread -----------------
template<bool GATHER>
__device__ __forceinline__ void ldg_tile(const float* __restrict__ src, int ld,
                                         int rowBase, int k0, int tid, float4* reg)
{
    #pragma unroll
    for (int i = 0; i < 4; i++) {
        int f = tid + (i << 8);          // 0..1023 float4 slots (128 rows x 8)
        int r = f >> 3;
        int c = (f & 7) << 2;
        int gm = rowBase + r;
        long sr;
        if (GATHER) {
            int s = gm & 2047;
            sr = (long)(gm >> 11) * L_ + ((s >> 9) << 11) + ((s & 511) << 2);
        } else {
            sr = gm;
        }
        reg[i] = *(const float4*)(src + sr * (long)ld + k0 + c);
    }
}

// ---------------- regs -> smem (fp16 cvt, one plane) -----------------------
__device__ __forceinline__ void sts_cvt(const float4* reg, char* pP, int tid)
{
    #pragma unroll
    for (int i = 0; i < 4; i++) {
        float4 v = reg[i];
        int f = tid + (i << 8);
        int r = f >> 3;
        int c = (f & 7) << 2;
        __half2 h01 = __floats2half2_rn(v.x, v.y);
        __half2 h23 = __floats2half2_rn(v.z, v.w);
        uint32_t off = (uint32_t)(r * ROWB + (c << 1));
        uint2 hv;
        hv.x = *(uint32_t*)&h01; hv.y = *(uint32_t*)&h23;
        *(uint2*)(pP + off) = hv;
    }
}

// ---------------- shared mainloop body -------------------------------------
struct Frag { float acc[2][8][4]; };

__device__ __forceinline__ void mma_chunk(uint32_t sb, int aRow, int aKof,
                                          int bRow, int bKof, Frag& fr)
{
    const uint32_t aP = sb, bP = sb + PLANE;
    #pragma unroll
    for (int k16 = 0; k16 < 2; k16++) {
        const int kk = k16 << 4;
        uint32_t ah[2][4], bh[8][2];
        #pragma unroll
        for (int mt = 0; mt < 2; mt++) {
            uint32_t off = (uint32_t)((aRow + mt * 16) * ROWB + (kk + aKof) * 2);
            LDSM4(ah[mt], aP + off);
        }
        #pragma unroll
        for (int np = 0; np < 4; np++) {
            uint32_t off = (uint32_t)((bRow + np * 16) * ROWB + (kk + bKof) * 2);
            uint32_t r[4];
            LDSM4(r, bP + off);
            bh[np*2][0] = r[0]; bh[np*2][1] = r[1];
            bh[np*2+1][0] = r[2]; bh[np*2+1][1] = r[3];
        }
        #pragma unroll
        for (int mt = 0; mt < 2; mt++)
            #pragma unroll
            for (int nt = 0; nt < 8; nt++)
                MMA_F16(fr.acc[mt][nt], ah[mt], bh[nt]);
    }
}

// ---------------- generic GEMM (QK, PV): C = A B^T * alpha, fp32 out ------
__global__ void __launch_bounds__(256)
bf_gemm(const float* __restrict__ A, const float* __restrict__ Bm,
        float* __restrict__ C, int K, float alpha,
        long sAb, long sBb, long sCb, int ldA, int ldB, int ldC)
{
    extern __shared__ char sm[];
    const uint32_t smem_base = smem_u32(sm);
    const int tid  = threadIdx.x;
    const int wid  = tid >> 5;
    const int lane = tid & 31;
    const int warpM = wid & 3;
    const int warpN = wid >> 2;
    const int bz = blockIdx.z;

    A  += (long)bz * sAb;
    Bm += (long)bz * sBb;
    C  += (long)bz * sCb;

    const int bm0 = blockIdx.y * BM;
    const int bn0 = blockIdx.x * BN;
    const int NC  = K / BKF;

    Frag fr = {};
    float4 ra[4], rb[4];

    ldg_tile<false>(A,  ldA, bm0, 0, tid, ra);
    ldg_tile<false>(Bm, ldB, bn0, 0, tid, rb);
    sts_cvt(ra, sm, tid);
    sts_cvt(rb, sm + PLANE, tid);
    __syncthreads();

    const int aRow = warpM * 32 + (lane & 15);
    const int aKof = (lane >> 4) << 3;
    const int bRow = warpN * 64 + ((lane >> 4) << 3) + (lane & 7);
    const int bKof = ((lane >> 3) & 1) << 3;

    for (int c = 0; c < NC; c++) {
        const int buf = c & 1;
        if (c + 1 < NC) {
            ldg_tile<false>(A,  ldA, bm0, (c + 1) * BKF, tid, ra);
            ldg_tile<false>(Bm, ldB, bn0, (c + 1) * BKF, tid, rb);
        }
        mma_chunk(smem_base + buf * STAGE_B, aRow, aKof, bRow, bKof, fr);
        if (c + 1 < NC) {
            char* nb = sm + (buf ^ 1) * STAGE_B;
            sts_cvt(ra, nb, tid);
            sts_cvt(rb, nb + PLANE, tid);
        }
        __syncthreads();
    }

    const int groupID = lane >> 2, tig = lane & 3;
    #pragma unroll
    for (int mt = 0; mt < 2; mt++)
        #pragma unroll
        for (int nt = 0; nt < 8; nt++) {
            float* a = fr.acc[mt][nt];
            const int row = bm0 + warpM * 32 + mt * 16 + groupID;
            const int col = bn0 + warpN * 64 + nt * 8 + tig * 2;
            *(float2*)(C + (long)row * ldC + col) =
                make_float2(a[0] * alpha, a[1] * alpha);
            *(float2*)(C + (long)(row + 8) * ldC + col) =
                make_float2(a[2] * alpha, a[3] * alpha);
        }
}

// ---------------- merged projection GEMM (single launch, z selects) --------
struct ProjPtrs {
    const float *A0, *A1, *A2;
    const float *W0, *W1, *W2;
    float *Cq, *Ck, *vT;
};

__global__ void __launch_bounds__(256)
proj_gemm(ProjPtrs p)
{
    extern __shared__ char sm[];
    const uint32_t smem_base = smem_u32(sm);
    const int tid  = threadIdx.x;
    const int wid  = tid >> 5;
    const int lane = tid & 31;
    const int warpM = wid & 3;
    const int warpN = wid >> 2;
    const int z = blockIdx.z;

    const float* A  = (z == 0) ? p.A0 : (z == 1) ? p.A1 : p.A2;
    const float* Bm = (z == 0) ? p.W0 : (z == 1) ? p.W1 : p.W2;

    const int bm0 = blockIdx.y * BM;
    const int bn0 = blockIdx.x * BN;
    const int NC  = D_ / BKF;      // 24

    Frag fr = {};
    float4 ra[4], rb[4];

    ldg_tile<true >(A,  D_, bm0, 0, tid, ra);
    ldg_tile<false>(Bm, D_, bn0, 0, tid, rb);
    sts_cvt(ra, sm, tid);
    sts_cvt(rb, sm + PLANE, tid);
    __syncthreads();

    const int aRow = warpM * 32 + (lane & 15);
    const int aKof = (lane >> 4) << 3;
    const int bRow = warpN * 64 + ((lane >> 4) << 3) + (lane & 7);
    const int bKof = ((lane >> 3) & 1) << 3;

    for (int c = 0; c < NC; c++) {
        const int buf = c & 1;
        if (c + 1 < NC) {
            ldg_tile<true >(A,  D_, bm0, (c + 1) * BKF, tid, ra);
            ldg_tile<false>(Bm, D_, bn0, (c + 1) * BKF, tid, rb);
        }
        mma_chunk(smem_base + buf * STAGE_B, aRow, aKof, bRow, bKof, fr);
        if (c + 1 < NC) {
            char* nb = sm + (buf ^ 1) * STAGE_B;
            sts_cvt(ra, nb, tid);
            sts_cvt(rb, nb + PLANE, tid);
        }
        __syncthreads();
    }

    const int groupID = lane >> 2, tig = lane & 3;
    #pragma unroll
    for (int mt = 0; mt < 2; mt++)
        #pragma unroll
        for (int nt = 0; nt < 8; nt++) {
            float* a = fr.acc[mt][nt];
            const int row = bm0 + warpM * 32 + mt * 16 + groupID;
            const int col = bn0 + warpN * 64 + nt * 8 + tig * 2;
            if (z < 2) {
                float* C = z ? p.Ck : p.Cq;
                *(float2*)(C + (long)row * D_ + col) = make_float2(a[0], a[1]);
                *(float2*)(C + (long)(row + 8) * D_ + col) = make_float2(a[2], a[3]);
            } else {
                // vT: [b][n][tok]
                const int b2 = row >> 11, tok = row & 2047;
                long base = (long)b2 * D_ * LS_ + tok;
                #pragma unroll
                for (int e = 0; e < 4; e++) {
                    long off = base + (long)(col + (e & 1)) * LS_ + ((e >> 1) << 3);
                    p.vT[off] = a[e];
                }
            }
        }
}

// ======================= reductions / pointwise ============================
__device__ __forceinline__ float block_sum(float v) {
    __shared__ float sh[8];
    int lane = threadIdx.x & 31, w = threadIdx.x >> 5;
    #pragma unroll
    for (int o = 16; o > 0; o >>= 1) v += __shfl_xor_sync(0xffffffffu, v, o);
    __syncthreads();
    if (lane == 0) sh[w] = v;
    __syncthreads();
    float t = 0.f;
    #pragma unroll
    for (int i = 0; i < 8; i++) t += sh[i];
    return t;
}
__device__ __forceinline__ float block_max(float v) {
    __shared__ float sh[8];
    int lane = threadIdx.x & 31, w = threadIdx.x >> 5;
    #pragma unroll
    for (int o = 16; o > 0; o >>= 1) v = fmaxf(v, __shfl_xor_sync(0xffffffffu, v, o));
    __syncthreads();
    if (lane == 0) sh[w] = v;
    __syncthreads();
    float t = -3.4e38f;
    #pragma unroll
    for (int i = 0; i < 8; i++) t = fmaxf(t, sh[i]);
    return t;
}

// merged LayerNorm (in place) for q and k: blockIdx.y selects buffer
__global__ void __launch_bounds__(256)
ln_kernel(float* __restrict__ xq, float* __restrict__ xk,
          const float* __restrict__ gamma, const float* __restrict__ beta)
{
    float* x = blockIdx.y ? xk : xq;
    float* pp = x + (long)blockIdx.x * D_;
    int t = threadIdx.x;
    float v0 = pp[t], v1 = pp[t + 256], v2 = pp[t + 512];
    float mean = block_sum(v0 + v1 + v2) * (1.0f / D_);
    float d0 = v0 - mean, d1 = v1 - mean, d2 = v2 - mean;
    float var = block_sum(d0 * d0 + d1 * d1 + d2 * d2) * (1.0f / D_);
    float rstd = rsqrtf(var + 1e-5f);
    pp[t]       = d0 * rstd * gamma[t]       + beta[t];
    pp[t + 256] = d1 * rstd * gamma[t + 256] + beta[t + 256];
    pp[t + 512] = d2 * rstd * gamma[t + 512] + beta[t + 512];
}

__global__ void __launch_bounds__(256)
softmax2048_kernel(float* __restrict__ S)
{
    float* p = S + (long)blockIdx.x * LS_;
    int t = threadIdx.x;
    float v[8];
    float m = -3.4e38f;
    #pragma unroll
    for (int i = 0; i < 8; i++) { v[i] = p[t + i * 256]; m = fmaxf(m, v[i]); }
    m = block_max(m);
    float s = 0.f;
    #pragma unroll
    for (int i = 0; i < 8; i++) { v[i] = __expf(v[i] - m); s += v[i]; }
    s = block_sum(s);
    float inv = 1.0f / s;
    #pragma unroll
    for (int i = 0; i < 8; i++) p[t + i * 256] = v[i] * inv;
}

__global__ void __launch_bounds__(256)
softmax768_kernel(const float* __restrict__ O, float* __restrict__ out)
{
    const float* p = O   + (long)blockIdx.x * D_;
    float*       q = out + (long)blockIdx.x * D_;
    int t = threadIdx.x;
    float v0 = p[t], v1 = p[t + 256], v2 = p[t + 512];
    float m = block_max(fmaxf(v0, fmaxf(v1, v2)));
    v0 = __expf(v0 - m); v1 = __expf(v1 - m); v2 = __expf(v2 - m);
    float inv = 1.0f / block_sum(v0 + v1 + v2);
    q[t] = v0 * inv; q[t + 256] = v1 * inv; q[t + 512] = v2 * inv;
}

// ======================= launch ===========================================
extern "C" void kernel_launch(void* const* d_in, const int* in_sizes, int n_in,
                              void* d_out, int out_size)
{
    const float* Q     = (const float*)d_in[0];
    const float* K     = (const float*)d_in[1];
    const float* V     = (const float*)d_in[2];
    const float* Wq    = (const float*)d_in[3];
    const float* Wk    = (const float*)d_in[4];
    const float* Wv    = (const float*)d_in[5];
    const float* gamma = (const float*)d_in[6];
    const float* beta  = (const float*)d_in[7];
    float* out = (float*)d_out;

    float *gq, *gk, *gvT, *gs, *go;
    cudaGetSymbolAddress((void**)&gq,  g_q);
    cudaGetSymbolAddress((void**)&gk,  g_k);
    cudaGetSymbolAddress((void**)&gvT, g_vT);
    cudaGetSymbolAddress((void**)&gs,  g_s);
    cudaGetSymbolAddress((void**)&go,  g_o);

    cudaFuncSetAttribute(bf_gemm,   cudaFuncAttributeMaxDynamicSharedMemorySize, SMEMSZ);
    cudaFuncSetAttribute(proj_gemm, cudaFuncAttributeMaxDynamicSharedMemorySize, SMEMSZ);

    const dim3 blk(256);
    const float scale = 1.0f / sqrtf((float)D_);

    // 1. merged projections (one launch, z in {q,k,v}): C = gather(X) @ W^T
    ProjPtrs pp;
    pp.A0 = Q;  pp.A1 = K;  pp.A2 = V;
    pp.W0 = Wq; pp.W1 = Wk; pp.W2 = Wv;
    pp.Cq = gq; pp.Ck = gk; pp.vT = gvT;
    proj_gemm<<<dim3(D_ / BN, MTOT / BM, 3), blk, SMEMSZ>>>(pp);

    // 2. merged qk LayerNorm
    ln_kernel<<<dim3(MTOT, 2), blk>>>(gq, gk, gamma, beta);

    // 3. S = q k^T * scale (per batch, both K-major)
    bf_gemm<<<dim3(LS_ / BN, LS_ / BM, B_), blk, SMEMSZ>>>(
        gq, gk, gs, D_, scale,
        (long)LS_ * D_, (long)LS_ * D_, (long)LS_ * LS_, D_, D_, LS_);

    // 4. row softmax
    softmax2048_kernel<<<B_ * LS_, blk>>>(gs);

    // 5. O = P v  (B = vT, K-major rows of length 2048)
    bf_gemm<<<dim3(D_ / BN, LS_ / BM, B_), blk, SMEMSZ>>>(
        gs, gvT, go, LS_, 1.0f,
        (long)LS_ * LS_, (long)D_ * LS_, (long)LS_ * D_, LS_, LS_, D_);

    // 6. feature softmax -> out
    softmax768_kernel<<<MTOT, blk>>>(go, out);
}

// round 16
// speedup vs baseline: 2.3992x; 1.3763x over previous
#include <cuda_runtime.h>
#include <cuda_fp16.h>
#include <math.h>
#include <stdint.h>

// ---------------------------------------------------------------------------
// DilatedAttention, single-pass fp16 mma.sync GEMMs, fp16 operands in GMEM.
// All fp32->fp16 conversion hoisted to producers (bit-identical numerics to
// the 526us R14 kernel; operand bytes through L2/DRAM halved).
//   B=4, L=8192, D=768, SEG=2048, RATE=4 -> Ls=2048/batch, MTOT=8192
// ---------------------------------------------------------------------------

#define B_      4
#define L_      8192
#define D_      768
#define LS_     2048
#define MTOT    (B_ * LS_)

typedef __half h16;

// ---------------- device scratch (allocation-free rule) --------------------
__device__ h16   g_x16[3L * MTOT * D_];      // gathered+cvt X for q,k,v
__device__ h16   g_w16[3L * D_ * D_];        // cvt weights
__device__ float g_q[(long)MTOT * D_];       // q proj fp32 (LN input); later O
__device__ float g_k[(long)MTOT * D_];       // k proj fp32 (LN input)
__device__ h16   g_q16[(long)MTOT * D_];     // LN(q) fp16
__device__ h16   g_k16[(long)MTOT * D_];     // LN(k) fp16
__device__ h16   g_vT16[(long)B_ * D_ * LS_];// projected V, transposed, fp16
__device__ float g_s[(long)B_ * LS_ * LS_];  // 64 MB scores fp32
__device__ h16   g_p16[(long)B_ * LS_ * LS_];// softmax(S) fp16

// ---------------- smem geometry -------------------------------------------
#define BM      128
#define BN      128
#define BKF     32                   // K per tile chunk (elements)
#define ROWB    80                   // 64B data + 16B pad (LDSM conflict-free)
#define PLANE   (128 * ROWB)         // 10240 B
#define STAGE_B (2 * PLANE)          // A, B = 20480 B
#define SMEMSZ  (2 * STAGE_B)        // double buffered = 40960 B

__device__ __forceinline__ uint32_t smem_u32(const void* p) {
    uint32_t a;
    asm("{ .reg .u64 t; cvta.to.shared.u64 t, %1; cvt.u32.u64 %0, t; }" : "=r"(a) : "l"(p));
    return a;
}

#define LDSM4(r, addr) \
    asm volatile("ldmatrix.sync.aligned.m8n8.x4.shared.b16 {%0,%1,%2,%3}, [%4];" \
        : "=r"((r)[0]), "=r"((r)[1]), "=r"((r)[2]), "=r"((r)[3]) : "r"(addr))

#define MMA_F16(d, a, b) \
    asm volatile("mma.sync.aligned.m16n8k16.row.col.f32.f16.f16.f32 " \
        "{%0,%1,%2,%3}, {%4,%5,%6,%7}, {%8,%9}, {%0,%1,%2,%3};" \
        : "+f"((d)[0]), "+f"((d)[1]), "+f"((d)[2]), "+f"((d)[3]) \
        : "r"((a)[0]), "r"((a)[1]), "r"((a)[2]), "r"((a)[3]), "r"((b)[0]), "r"((b)[1]))

// ---------------- fp16 gmem -> regs: 2 x 16B per thread per plane ----------
// chunk w = tid + j*256 (j=0,1): r = w>>2 (row 0..127), ck = w&3 (16B col)
__device__ __forceinline__ void ldg_h(const h16* __restrict__ src, int ld,
                                      int row0, int k0, int tid, uint4* rg)
{
    #pragma unroll
    for (int j = 0; j < 2; j++) {
        int w = tid + (j << 8);
        int r = w >> 2;
        int ck = w & 3;
        rg[j] = *(const uint4*)(src + (long)(row0 + r) * ld + k0 + ck * 8);
    }
}

__device__ __forceinline__ void sts_h(const uint4* rg, char* pP, int tid)
{
    #pragma unroll
    for (int j = 0; j < 2; j++) {
        int w = tid + (j << 8);
        int r = w >> 2;
        int ck = w & 3;
        *(uint4*)(pP + (uint32_t)(r * ROWB + ck * 16)) = rg[j];
    }
}

// ---------------- shared mainloop body -------------------------------------
struct Frag { float acc[2][8][4]; };

__device__ __forceinline__ void mma_chunk(uint32_t sb, int aRow, int aKof,
                                          int bRow, int bKof, Frag& fr)
{
    const uint32_t aP = sb, bP = sb + PLANE;
    #pragma unroll
    for (int k16 = 0; k16 < 2; k16++) {
        const int kk = k16 << 4;
        uint32_t ah[2][4], bh[8][2];
        #pragma unroll
        for (int mt = 0; mt < 2; mt++) {
            uint32_t off = (uint32_t)((aRow + mt * 16) * ROWB + (kk + aKof) * 2);
            LDSM4(ah[mt], aP + off);
        }
        #pragma unroll
        for (int np = 0; np < 4; np++) {
            uint32_t off = (uint32_t)((bRow + np * 16) * ROWB + (kk + bKof) * 2);
            uint32_t r[4];
            LDSM4(r, bP + off);
            bh[np*2][0] = r[0]; bh[np*2][1] = r[1];
            bh[np*2+1][0] = r[2]; bh[np*2+1][1] = r[3];
        }
        #pragma unroll
        for (int mt = 0; mt < 2; mt++)
            #pragma unroll
            for (int nt = 0; nt < 8; nt++)
                MMA_F16(fr.acc[mt][nt], ah[mt], bh[nt]);
    }
}

// ---------------- generic GEMM (QK, PV): C = A B^T * alpha, fp32 out -------
__global__ void __launch_bounds__(256)
hgemm(const h16* __restrict__ A, const h16* __restrict__ Bm,
      float* __restrict__ C, int K, float alpha,
      long sAb, long sBb, long sCb, int ldA, int ldB, int ldC)
{
    extern __shared__ char sm[];
    const uint32_t smem_base = smem_u32(sm);
    const int tid  = threadIdx.x;
    const int wid  = tid >> 5;
    const int lane = tid & 31;
    const int warpM = wid & 3;
    const int warpN = wid >> 2;
    const int bz = blockIdx.z;

    A  += (long)bz * sAb;
    Bm += (long)bz * sBb;
    C  += (long)bz * sCb;

    const int bm0 = blockIdx.y * BM;
    const int bn0 = blockIdx.x * BN;
    const int NC  = K / BKF;

    Frag fr = {};
    uint4 ra[2], rb[2];

    ldg_h(A,  ldA, bm0, 0, tid, ra);
    ldg_h(Bm, ldB, bn0, 0, tid, rb);
    sts_h(ra, sm, tid);
    sts_h(rb, sm + PLANE, tid);
    __syncthreads();

    const int aRow = warpM * 32 + (lane & 15);
    const int aKof = (lane >> 4) << 3;
    const int bRow = warpN * 64 + ((lane >> 4) << 3) + (lane & 7);
    const int bKof = ((lane >> 3) & 1) << 3;

    for (int c = 0; c < NC; c++) {
        const int buf = c & 1;
        if (c + 1 < NC) {
            ldg_h(A,  ldA, bm0, (c + 1) * BKF, tid, ra);
            ldg_h(Bm, ldB, bn0, (c + 1) * BKF, tid, rb);
        }
        mma_chunk(smem_base + buf * STAGE_B, aRow, aKof, bRow, bKof, fr);
        if (c + 1 < NC) {
            char* nb = sm + (buf ^ 1) * STAGE_B;
            sts_h(ra, nb, tid);
            sts_h(rb, nb + PLANE, tid);
        }
        __syncthreads();
    }

    const int groupID = lane >> 2, tig = lane & 3;
    #pragma unroll
    for (int mt = 0; mt < 2; mt++)
        #pragma unroll
        for (int nt = 0; nt < 8; nt++) {
            float* a = fr.acc[mt][nt];
            const int row = bm0 + warpM * 32 + mt * 16 + groupID;
            const int col = bn0 + warpN * 64 + nt * 8 + tig * 2;
            *(float2*)(C + (long)row * ldC + col) =
                make_float2(a[0] * alpha, a[1] * alpha);
            *(float2*)(C + (long)(row + 8) * ldC + col) =
                make_float2(a[2] * alpha, a[3] * alpha);
        }
}

// ---------------- projections (single launch, z selects; fp16 operands) ----
__global__ void __launch_bounds__(256)
proj_gemm(const h16* __restrict__ X16, const h16* __restrict__ W16,
          float* __restrict__ Cq, float* __restrict__ Ck, h16* __restrict__ vT)
{
    extern __shared__ char sm[];
    const uint32_t smem_base = smem_u32(sm);
    const int tid  = threadIdx.x;
    const int wid  = tid >> 5;
    const int lane = tid & 31;
    const int warpM = wid & 3;
    const int warpN = wid >> 2;
    const int z = blockIdx.z;

    const h16* A  = X16 + (long)z * MTOT * D_;
    const h16* Bm = W16 + (long)z * D_ * D_;

    const int bm0 = blockIdx.y * BM;
    const int bn0 = blockIdx.x * BN;
    const int NC  = D_ / BKF;      // 24

    Frag fr = {};
    uint4 ra[2], rb[2];

    ldg_h(A,  D_, bm0, 0, tid, ra);
    ldg_h(Bm, D_, bn0, 0, tid, rb);
    sts_h(ra, sm, tid);
    sts_h(rb, sm + PLANE, tid);
    __syncthreads();

    const int aRow = warpM * 32 + (lane & 15);
    const int aKof = (lane >> 4) << 3;
    const int bRow = warpN * 64 + ((lane >> 4) << 3) + (lane & 7);
    const int bKof = ((lane >> 3) & 1) << 3;

    for (int c = 0; c < NC; c++) {
        const int buf = c & 1;
        if (c + 1 < NC) {
            ldg_h(A,  D_, bm0, (c + 1) * BKF, tid, ra);
            ldg_h(Bm, D_, bn0, (c + 1) * BKF, tid, rb);
        }
        mma_chunk(smem_base + buf * STAGE_B, aRow, aKof, bRow, bKof, fr);
        if (c + 1 < NC) {
            char* nb = sm + (buf ^ 1) * STAGE_B;
            sts_h(ra, nb, tid);
            sts_h(rb, nb + PLANE, tid);
        }
        __syncthreads();
    }

    const int groupID = lane >> 2, tig = lane & 3;
    #pragma unroll
    for (int mt = 0; mt < 2; mt++)
        #pragma unroll
        for (int nt = 0; nt < 8; nt++) {
            float* a = fr.acc[mt][nt];
            const int row = bm0 + warpM * 32 + mt * 16 + groupID;
            const int col = bn0 + warpN * 64 + nt * 8 + tig * 2;
            if (z < 2) {
                float* C = z ? Ck : Cq;
                *(float2*)(C + (long)row * D_ + col) = make_float2(a[0], a[1]);
                *(float2*)(C + (long)(row + 8) * D_ + col) = make_float2(a[2], a[3]);
            } else {
                // vT fp16: [b][n][tok]
                const int b2 = row >> 11, tok = row & 2047;
                long base = (long)b2 * D_ * LS_ + tok;
                #pragma unroll
                for (int e = 0; e < 4; e++) {
                    long off = base + (long)(col + (e & 1)) * LS_ + ((e >> 1) << 3);
                    vT[off] = __float2half_rn(a[e]);
                }
            }
        }
}

// ======================= converts / pointwise ==============================
// gather + cvt X (z in {Q,K,V}) -> contiguous fp16 [MTOT, D]
__global__ void __launch_bounds__(256)
gather_cvt(const float* __restrict__ X0, const float* __restrict__ X1,
           const float* __restrict__ X2, h16* __restrict__ dst)
{
    const int z = blockIdx.y;
    const float* src = (z == 0) ? X0 : (z == 1) ? X1 : X2;
    h16* d = dst + (long)z * MTOT * D_;
    long idx = (long)blockIdx.x * 256 + threadIdx.x;     // float4 slots
    if (idx >= (long)MTOT * (D_ / 4)) return;
    int r = (int)(idx / (D_ / 4));
    int c = (int)(idx % (D_ / 4)) * 4;
    int s = r & 2047;
    long sr = (long)(r >> 11) * L_ + ((s >> 9) << 11) + ((s & 511) << 2);
    float4 v = *(const float4*)(src + sr * (long)D_ + c);
    __half2 h01 = __floats2half2_rn(v.x, v.y);
    __half2 h23 = __floats2half2_rn(v.z, v.w);
    uint2 hv; hv.x = *(uint32_t*)&h01; hv.y = *(uint32_t*)&h23;
    *(uint2*)(d + (long)r * D_ + c) = hv;
}

// cvt weights (z in {Wq,Wk,Wv}) -> fp16 [D, D]
__global__ void __launch_bounds__(256)
w_cvt(const float* __restrict__ W0, const float* __restrict__ W1,
      const float* __restrict__ W2, h16* __restrict__ dst)
{
    const int z = blockIdx.y;
    const float* src = (z == 0) ? W0 : (z == 1) ? W1 : W2;
    h16* d = dst + (long)z * D_ * D_;
    long idx = (long)blockIdx.x * 256 + threadIdx.x;
    if (idx >= (long)D_ * (D_ / 4)) return;
    long off = idx * 4;
    float4 v = *(const float4*)(src + off);
    __half2 h01 = __floats2half2_rn(v.x, v.y);
    __half2 h23 = __floats2half2_rn(v.z, v.w);
    uint2 hv; hv.x = *(uint32_t*)&h01; hv.y = *(uint32_t*)&h23;
    *(uint2*)(d + off) = hv;
}

__device__ __forceinline__ float block_sum(float v) {
    __shared__ float sh[8];
    int lane = threadIdx.x & 31, w = threadIdx.x >> 5;
    #pragma unroll
    for (int o = 16; o > 0; o >>= 1) v += __shfl_xor_sync(0xffffffffu, v, o);
    __syncthreads();
    if (lane == 0) sh[w] = v;
    __syncthreads();
    float t = 0.f;
    #pragma unroll
    for (int i = 0; i < 8; i++) t += sh[i];
    return t;
}
__device__ __forceinline__ float block_max(float v) {
    __shared__ float sh[8];
    int lane = threadIdx.x & 31, w = threadIdx.x >> 5;
    #pragma unroll
    for (int o = 16; o > 0; o >>= 1) v = fmaxf(v, __shfl_xor_sync(0xffffffffu, v, o));
    __syncthreads();
    if (lane == 0) sh[w] = v;
    __syncthreads();
    float t = -3.4e38f;
    #pragma unroll
    for (int i = 0; i < 8; i++) t = fmaxf(t, sh[i]);
    return t;
}

// merged LayerNorm: reads fp32 proj, writes fp16 (blockIdx.y selects q/k)
__global__ void __launch_bounds__(256)
ln_kernel(const float* __restrict__ xq, const float* __restrict__ xk,
          h16* __restrict__ q16, h16* __restrict__ k16,
          const float* __restrict__ gamma, const float* __restrict__ beta)
{
    const float* x = blockIdx.y ? xk : xq;
    h16* o = blockIdx.y ? k16 : q16;
    const float* pp = x + (long)blockIdx.x * D_;
    long ob = (long)blockIdx.x * D_;
    int t = threadIdx.x;
    float v0 = pp[t], v1 = pp[t + 256], v2 = pp[t + 512];
    float mean = block_sum(v0 + v1 + v2) * (1.0f / D_);
    float d0 = v0 - mean, d1 = v1 - mean, d2 = v2 - mean;
    float var = block_sum(d0 * d0 + d1 * d1 + d2 * d2) * (1.0f / D_);
    float rstd = rsqrtf(var + 1e-5f);
    o[ob + t]       = __float2half_rn(d0 * rstd * gamma[t]       + beta[t]);
    o[ob + t + 256] = __float2half_rn(d1 * rstd * gamma[t + 256] + beta[t + 256]);
    o[ob + t + 512] = __float2half_rn(d2 * rstd * gamma[t + 512] + beta[t + 512]);
}

// row softmax (2048): reads fp32 S, writes fp16 P
__global__ void __launch_bounds__(256)
softmax2048_kernel(const float* __restrict__ S, h16* __restrict__ P)
{
    const float* p = S + (long)blockIdx.x * LS_;
    long ob = (long)blockIdx.x * LS_;
    int t = threadIdx.x;
    float v[8];
    float m = -3.4e38f;
    #pragma unroll
    for (int i = 0; i < 8; i++) { v[i] = p[t + i * 256]; m = fmaxf(m, v[i]); }
    m = block_max(m);
    float s = 0.f;
    #pragma unroll
    for (int i = 0; i < 8; i++) { v[i] = __expf(v[i] - m); s += v[i]; }
    s = block_sum(s);
    float inv = 1.0f / s;
    #pragma unroll
    for (int i = 0; i < 8; i++)
        P[ob + t + i * 256] = __float2half_rn(v[i] * inv);
}

__global__ void __launch_bounds__(256)
softmax768_kernel(const float* __restrict__ O, float* __restrict__ out)
{
    const float* p = O   + (long)blockIdx.x * D_;
    float*       q = out + (long)blockIdx.x * D_;
    int t = threadIdx.x;
    float v0 = p[t], v1 = p[t + 256], v2 = p[t + 512];
    float m = block_max(fmaxf(v0, fmaxf(v1, v2)));
    v0 = __expf(v0 - m); v1 = __expf(v1 - m); v2 = __expf(v2 - m);
    float inv = 1.0f / block_sum(v0 + v1 + v2);
    q[t] = v0 * inv; q[t + 256] = v1 * inv; q[t + 512] = v2 * inv;
}

// ======================= launch ===========================================
extern "C" void kernel_launch(void* const* d_in, const int* in_sizes, int n_in,
                              void* d_out, int out_size)
{
    const float* Q     = (const float*)d_in[0];
    const float* K     = (const float*)d_in[1];
    const float* V     = (const float*)d_in[2];
    const float* Wq    = (const float*)d_in[3];
    const float* Wk    = (const float*)d_in[4];
    const float* Wv    = (const float*)d_in[5];
    const float* gamma = (const float*)d_in[6];
    const float* beta  = (const float*)d_in[7];
    float* out = (float*)d_out;

    h16 *x16, *w16, *q16, *k16, *vT16, *p16;
    float *gq, *gk, *gs;
    cudaGetSymbolAddress((void**)&x16,  g_x16);
    cudaGetSymbolAddress((void**)&w16,  g_w16);
    cudaGetSymbolAddress((void**)&q16,  g_q16);
    cudaGetSymbolAddress((void**)&k16,  g_k16);
    cudaGetSymbolAddress((void**)&vT16, g_vT16);
    cudaGetSymbolAddress((void**)&p16,  g_p16);
    cudaGetSymbolAddress((void**)&gq,   g_q);
    cudaGetSymbolAddress((void**)&gk,   g_k);
    cudaGetSymbolAddress((void**)&gs,   g_s);
    float* go = gq;   // O reuses q-projection buffer (dead after LN)

    cudaFuncSetAttribute(hgemm,     cudaFuncAttributeMaxDynamicSharedMemorySize, SMEMSZ);
    cudaFuncSetAttribute(proj_gemm, cudaFuncAttributeMaxDynamicSharedMemorySize, SMEMSZ);

    const dim3 blk(256);
    const float scale = 1.0f / sqrtf((float)D_);
    const int gX = (MTOT * (D_ / 4) + 255) / 256;
    const int gW = (D_ * (D_ / 4) + 255) / 256;

    // 0. gather+cvt X; cvt W (fp16 operand planes)
    gather_cvt<<<dim3(gX, 3), blk>>>(Q, K, V, x16);
    w_cvt<<<dim3(gW, 3), blk>>>(Wq, Wk, Wv, w16);

    // 1. merged projections (z in {q,k,v}), fp16 operands
    proj_gemm<<<dim3(D_ / BN, MTOT / BM, 3), blk, SMEMSZ>>>(x16, w16, gq, gk, vT16);

    // 2. merged LN -> fp16 q16/k16
    ln_kernel<<<dim3(MTOT, 2), blk>>>(gq, gk, q16, k16, gamma, beta);

    // 3. S = q k^T * scale (per batch)
    hgemm<<<dim3(LS_ / BN, LS_ / BM, B_), blk, SMEMSZ>>>(
        q16, k16, gs, D_, scale,
        (long)LS_ * D_, (long)LS_ * D_, (long)LS_ * LS_, D_, D_, LS_);

    // 4. row softmax -> fp16 P
    softmax2048_kernel<<<B_ * LS_, blk>>>(gs, p16);

    // 5. O = P v (fp16 operands, K=2048)
    hgemm<<<dim3(D_ / BN, LS_ / BM, B_), blk, SMEMSZ>>>(
        p16, vT16, go, LS_, 1.0f,
        (long)LS_ * LS_, (long)D_ * LS_, (long)LS_ * D_, LS_, LS_, D_);

    // 6. feature softmax -> out
    softmax768_kernel<<<MTOT, blk>>>(go, out);
}

// round 17
// speedup vs baseline: 2.5856x; 1.0777x over previous
#include <cuda_runtime.h>
#include <cuda_fp16.h>
#include <math.h>
#include <stdint.h>

// ---------------------------------------------------------------------------
// DilatedAttention, single-pass fp16 mma.sync GEMMs, fp16 operands in GMEM,
// 4-stage cp.async pipeline (80KB smem, 2 CTA/SM), warp-per-row pointwise.
//   B=4, L=8192, D=768, SEG=2048, RATE=4 -> Ls=2048/batch, MTOT=8192
// ---------------------------------------------------------------------------

#define B_      4
#define L_      8192
#define D_      768
#define LS_     2048
#define MTOT    (B_ * LS_)

typedef __half h16;

// ---------------- device scratch (allocation-free rule) --------------------
__device__ h16   g_x16[3L * MTOT * D_];      // gathered+cvt X for q,k,v
__device__ h16   g_w16[3L * D_ * D_];        // cvt weights
__device__ float g_q[(long)MTOT * D_];       // q proj fp32 (LN input); later O
__device__ float g_k[(long)MTOT * D_];       // k proj fp32 (LN input)
__device__ h16   g_q16[(long)MTOT * D_];     // LN(q) fp16
__device__ h16   g_k16[(long)MTOT * D_];     // LN(k) fp16
__device__ h16   g_vT16[(long)B_ * D_ * LS_];// projected V, transposed, fp16
__device__ float g_s[(long)B_ * LS_ * LS_];  // 64 MB scores fp32
__device__ h16   g_p16[(long)B_ * LS_ * LS_];// softmax(S) fp16

// ---------------- smem geometry -------------------------------------------
#define BM      128
#define BN      128
#define BKF     32                   // K per tile chunk (elements)
#define ROWB    80                   // 64B data + 16B pad (LDSM conflict-free)
#define PLANE   (128 * ROWB)         // 10240 B
#define STAGE_B (2 * PLANE)          // A, B = 20480 B
#define STAGES  4
#define SMEMSZ  (STAGES * STAGE_B)   // 81920 B -> 2 CTA/SM

__device__ __forceinline__ uint32_t smem_u32(const void* p) {
    uint32_t a;
    asm("{ .reg .u64 t; cvta.to.shared.u64 t, %1; cvt.u32.u64 %0, t; }" : "=r"(a) : "l"(p));
    return a;
}

#define LDSM4(r, addr) \
    asm volatile("ldmatrix.sync.aligned.m8n8.x4.shared.b16 {%0,%1,%2,%3}, [%4];" \
        : "=r"((r)[0]), "=r"((r)[1]), "=r"((r)[2]), "=r"((r)[3]) : "r"(addr))

#define MMA_F16(d, a, b) \
    asm volatile("mma.sync.aligned.m16n8k16.row.col.f32.f16.f16.f32 " \
        "{%0,%1,%2,%3}, {%4,%5,%6,%7}, {%8,%9}, {%0,%1,%2,%3};" \
        : "+f"((d)[0]), "+f"((d)[1]), "+f"((d)[2]), "+f"((d)[3]) \
        : "r"((a)[0]), "r"((a)[1]), "r"((a)[2]), "r"((a)[3]), "r"((b)[0]), "r"((b)[1]))

#define CP16(dst, src) \
    asm volatile("cp.async.cg.shared.global [%0], [%1], 16;" :: "r"(dst), "l"(src))
#define CP_COMMIT() asm volatile("cp.async.commit_group;" ::: "memory")
#define CP_WAIT2()  asm volatile("cp.async.wait_group 2;" ::: "memory")

// ---------------- cp.async stage fill: A + B planes, 4 x 16B per thread ----
__device__ __forceinline__ void issue_stage(
    const h16* __restrict__ A, const h16* __restrict__ Bm,
    int ldA, int ldB, int bm0, int bn0, int k0, uint32_t stage, int tid)
{
    #pragma unroll
    for (int j = 0; j < 2; j++) {
        int w = tid + (j << 8);          // 0..511
        int r = w >> 2;                  // row 0..127
        int ck = w & 3;                  // 16B col
        CP16(stage + (uint32_t)(r * ROWB + ck * 16),
             A + (long)(bm0 + r) * ldA + k0 + ck * 8);
    }
    #pragma unroll
    for (int j = 0; j < 2; j++) {
        int w = tid + (j << 8);
        int r = w >> 2;
        int ck = w & 3;
        CP16(stage + PLANE + (uint32_t)(r * ROWB + ck * 16),
             Bm + (long)(bn0 + r) * ldB + k0 + ck * 8);
    }
}

// ---------------- shared mainloop body -------------------------------------
struct Frag { float acc[2][8][4]; };

__device__ __forceinline__ void mma_chunk(uint32_t sb, int aRow, int aKof,
                                          int bRow, int bKof, Frag& fr)
{
    const uint32_t aP = sb, bP = sb + PLANE;
    #pragma unroll
    for (int k16 = 0; k16 < 2; k16++) {
        const int kk = k16 << 4;
        uint32_t ah[2][4], bh[8][2];
        #pragma unroll
        for (int mt = 0; mt < 2; mt++) {
            uint32_t off = (uint32_t)((aRow + mt * 16) * ROWB + (kk + aKof) * 2);
            LDSM4(ah[mt], aP + off);
        }
        #pragma unroll
        for (int np = 0; np < 4; np++) {
            uint32_t off = (uint32_t)((bRow + np * 16) * ROWB + (kk + bKof) * 2);
            uint32_t r[4];
            LDSM4(r, bP + off);
            bh[np*2][0] = r[0]; bh[np*2][1] = r[1];
            bh[np*2+1][0] = r[2]; bh[np*2+1][1] = r[3];
        }
        #pragma unroll
        for (int mt = 0; mt < 2; mt++)
            #pragma unroll
            for (int nt = 0; nt < 8; nt++)
                MMA_F16(fr.acc[mt][nt], ah[mt], bh[nt]);
    }
}

// ---------------- generic GEMM (QK, PV): C = A B^T * alpha, fp32 out -------
__global__ void __launch_bounds__(256)
hgemm(const h16* __restrict__ A, const h16* __restrict__ Bm,
      float* __restrict__ C, int K, float alpha,
      long sAb, long sBb, long sCb, int ldA, int ldB, int ldC)
{
    extern __shared__ char sm[];
    const uint32_t smem_base = smem_u32(sm);
    const int tid  = threadIdx.x;
    const int wid  = tid >> 5;
    const int lane = tid & 31;
    const int warpM = wid & 3;
    const int warpN = wid >> 2;
    const int bz = blockIdx.z;

    A  += (long)bz * sAb;
    Bm += (long)bz * sBb;
    C  += (long)bz * sCb;

    const int bm0 = blockIdx.y * BM;
    const int bn0 = blockIdx.x * BN;
    const int NC  = K / BKF;

    Frag fr = {};

    // prologue: stages 0..2
    #pragma unroll
    for (int s = 0; s < 3; s++) {
        issue_stage(A, Bm, ldA, ldB, bm0, bn0, s * BKF,
                    smem_base + s * STAGE_B, tid);
        CP_COMMIT();
    }

    const int aRow = warpM * 32 + (lane & 15);
    const int aKof = (lane >> 4) << 3;
    const int bRow = warpN * 64 + ((lane >> 4) << 3) + (lane & 7);
    const int bKof = ((lane >> 3) & 1) << 3;

    for (int c = 0; c < NC; c++) {
        CP_WAIT2();
        __syncthreads();
        const int nxt = c + 3;
        if (nxt < NC)
            issue_stage(A, Bm, ldA, ldB, bm0, bn0, nxt * BKF,
                        smem_base + (nxt & 3) * STAGE_B, tid);
        CP_COMMIT();
        mma_chunk(smem_base + (c & 3) * STAGE_B, aRow, aKof, bRow, bKof, fr);
    }

    const int groupID = lane >> 2, tig = lane & 3;
    #pragma unroll
    for (int mt = 0; mt < 2; mt++)
        #pragma unroll
        for (int nt = 0; nt < 8; nt++) {
            float* a = fr.acc[mt][nt];
            const int row = bm0 + warpM * 32 + mt * 16 + groupID;
            const int col = bn0 + warpN * 64 + nt * 8 + tig * 2;
            *(float2*)(C + (long)row * ldC + col) =
                make_float2(a[0] * alpha, a[1] * alpha);
            *(float2*)(C + (long)(row + 8) * ldC + col) =
                make_float2(a[2] * alpha, a[3] * alpha);
        }
}

// ---------------- projections (single launch, z selects; fp16 operands) ----
__global__ void __launch_bounds__(256)
proj_gemm(const h16* __restrict__ X16, const h16* __restrict__ W16,
          float* __restrict__ Cq, float* __restrict__ Ck, h16* __restrict__ vT)
{
    extern __shared__ char sm[];
    const uint32_t smem_base = smem_u32(sm);
    const int tid  = threadIdx.x;
    const int wid  = tid >> 5;
    const int lane = tid & 31;
    const int warpM = wid & 3;
    const int warpN = wid >> 2;
    const int z = blockIdx.z;

    const h16* A  = X16 + (long)z * MTOT * D_;
    const h16* Bm = W16 + (long)z * D_ * D_;

    const int bm0 = blockIdx.y * BM;
    const int bn0 = blockIdx.x * BN;
    const int NC  = D_ / BKF;      // 24

    Frag fr = {};

    #pragma unroll
    for (int s = 0; s < 3; s++) {
        issue_stage(A, Bm, D_, D_, bm0, bn0, s * BKF,
                    smem_base + s * STAGE_B, tid);
        CP_COMMIT();
    }

    const int aRow = warpM * 32 + (lane & 15);
    const int aKof = (lane >> 4) << 3;
    const int bRow = warpN * 64 + ((lane >> 4) << 3) + (lane & 7);
    const int bKof = ((lane >> 3) & 1) << 3;

    for (int c = 0; c < NC; c++) {
        CP_WAIT2();
        __syncthreads();
        const int nxt = c + 3;
        if (nxt < NC)
            issue_stage(A, Bm, D_, D_, bm0, bn0, nxt * BKF,
                        smem_base + (nxt & 3) * STAGE_B, tid);
        CP_COMMIT();
        mma_chunk(smem_base + (c & 3) * STAGE_B, aRow, aKof, bRow, bKof, fr);
    }

    const int groupID = lane >> 2, tig = lane & 3;
    #pragma unroll
    for (int mt = 0; mt < 2; mt++)
        #pragma unroll
        for (int nt = 0; nt < 8; nt++) {
            float* a = fr.acc[mt][nt];
            const int row = bm0 + warpM * 32 + mt * 16 + groupID;
            const int col = bn0 + warpN * 64 + nt * 8 + tig * 2;
            if (z < 2) {
                float* C = z ? Ck : Cq;
                *(float2*)(C + (long)row * D_ + col) = make_float2(a[0], a[1]);
                *(float2*)(C + (long)(row + 8) * D_ + col) = make_float2(a[2], a[3]);
            } else {
                // vT fp16: [b][n][tok]
                const int b2 = row >> 11, tok = row & 2047;
                long base = (long)b2 * D_ * LS_ + tok;
                #pragma unroll
                for (int e = 0; e < 4; e++) {
                    long off = base + (long)(col + (e & 1)) * LS_ + ((e >> 1) << 3);
                    vT[off] = __float2half_rn(a[e]);
                }
            }
        }
}

// ======================= converts / warp-per-row pointwise =================
__device__ __forceinline__ float warp_sum(float v) {
    #pragma unroll
    for (int o = 16; o > 0; o >>= 1) v += __shfl_xor_sync(0xffffffffu, v, o);
    return v;
}
__device__ __forceinline__ float warp_max(float v) {
    #pragma unroll
    for (int o = 16; o > 0; o >>= 1) v = fmaxf(v, __shfl_xor_sync(0xffffffffu, v, o));
    return v;
}

// gather + cvt X (z in {Q,K,V}) -> contiguous fp16 [MTOT, D]
__global__ void __launch_bounds__(256)
gather_cvt(const float* __restrict__ X0, const float* __restrict__ X1,
           const float* __restrict__ X2, h16* __restrict__ dst)
{
    const int z = blockIdx.y;
    const float* src = (z == 0) ? X0 : (z == 1) ? X1 : X2;
    h16* d = dst + (long)z * MTOT * D_;
    long idx = (long)blockIdx.x * 256 + threadIdx.x;     // float4 slots
    if (idx >= (long)MTOT * (D_ / 4)) return;
    int r = (int)(idx / (D_ / 4));
    int c = (int)(idx % (D_ / 4)) * 4;
    int s = r & 2047;
    long sr = (long)(r >> 11) * L_ + ((s >> 9) << 11) + ((s & 511) << 2);
    float4 v = *(const float4*)(src + sr * (long)D_ + c);
    __half2 h01 = __floats2half2_rn(v.x, v.y);
    __half2 h23 = __floats2half2_rn(v.z, v.w);
    uint2 hv; hv.x = *(uint32_t*)&h01; hv.y = *(uint32_t*)&h23;
    *(uint2*)(d + (long)r * D_ + c) = hv;
}

// cvt weights (z in {Wq,Wk,Wv}) -> fp16 [D, D]
__global__ void __launch_bounds__(256)
w_cvt(const float* __restrict__ W0, const float* __restrict__ W1,
      const float* __restrict__ W2, h16* __restrict__ dst)
{
    const int z = blockIdx.y;
    const float* src = (z == 0) ? W0 : (z == 1) ? W1 : W2;
    h16* d = dst + (long)z * D_ * D_;
    long idx = (long)blockIdx.x * 256 + threadIdx.x;
    if (idx >= (long)D_ * (D_ / 4)) return;
    long off = idx * 4;
    float4 v = *(const float4*)(src + off);
    __half2 h01 = __floats2half2_rn(v.x, v.y);
    __half2 h23 = __floats2half2_rn(v.z, v.w);
    uint2 hv; hv.x = *(uint32_t*)&h01; hv.y = *(uint32_t*)&h23;
    *(uint2*)(d + off) = hv;
}

// LayerNorm, warp per row (768 = 6 float4/lane), no barriers.
// grid (MTOT/8, 2): y selects q/k.
__global__ void __launch_bounds__(256)
ln_kernel(const float* __restrict__ xq, const float* __restrict__ xk,
          h16* __restrict__ q16, h16* __restrict__ k16,
          const float* __restrict__ gamma, const float* __restrict__ beta)
{
    const int wid = threadIdx.x >> 5, lane = threadIdx.x & 31;
    const long row = (long)blockIdx.x * 8 + wid;
    const float* src = (blockIdx.y ? xk : xq) + row * D_;
    h16* dst = (blockIdx.y ? k16 : q16) + row * D_;

    float4 v[6];
    float s = 0.f;
    #pragma unroll
    for (int j = 0; j < 6; j++) {
        v[j] = ((const float4*)src)[lane + 32 * j];
        s += v[j].x + v[j].y + v[j].z + v[j].w;
    }
    float mean = warp_sum(s) * (1.0f / D_);
    float vs = 0.f;
    #pragma unroll
    for (int j = 0; j < 6; j++) {
        float a = v[j].x - mean, b = v[j].y - mean,
              c = v[j].z - mean, d = v[j].w - mean;
        vs += a * a + b * b + c * c + d * d;
    }
    float rstd = rsqrtf(warp_sum(vs) * (1.0f / D_) + 1e-5f);
    #pragma unroll
    for (int j = 0; j < 6; j++) {
        int f = lane + 32 * j;
        float4 g = ((const float4*)gamma)[f];
        float4 bb = ((const float4*)beta)[f];
        __half2 h01 = __floats2half2_rn((v[j].x - mean) * rstd * g.x + bb.x,
                                        (v[j].y - mean) * rstd * g.y + bb.y);
        __half2 h23 = __floats2half2_rn((v[j].z - mean) * rstd * g.z + bb.z,
                                        (v[j].w - mean) * rstd * g.w + bb.w);
        uint2 hv; hv.x = *(uint32_t*)&h01; hv.y = *(uint32_t*)&h23;
        *(uint2*)(dst + f * 4) = hv;
    }
}

// row softmax (2048), warp per row (16 float4/lane), writes fp16 P.
__global__ void __launch_bounds__(256)
softmax2048_kernel(const float* __restrict__ S, h16* __restrict__ P)
{
    const int wid = threadIdx.x >> 5, lane = threadIdx.x & 31;
    const long row = (long)blockIdx.x * 8 + wid;
    const float* p = S + row * LS_;
    h16* o = P + row * LS_;

    float4 v[16];
    float m = -3.4e38f;
    #pragma unroll
    for (int j = 0; j < 16; j++) {
        v[j] = ((const float4*)p)[lane + 32 * j];
        m = fmaxf(m, fmaxf(fmaxf(v[j].x, v[j].y), fmaxf(v[j].z, v[j].w)));
    }
    m = warp_max(m);
    float s = 0.f;
    #pragma unroll
    for (int j = 0; j < 16; j++) {
        v[j].x = __expf(v[j].x - m); v[j].y = __expf(v[j].y - m);
        v[j].z = __expf(v[j].z - m); v[j].w = __expf(v[j].w - m);
        s += v[j].x + v[j].y + v[j].z + v[j].w;
    }
    float inv = 1.0f / warp_sum(s);
    #pragma unroll
    for (int j = 0; j < 16; j++) {
        __half2 h01 = __floats2half2_rn(v[j].x * inv, v[j].y * inv);
        __half2 h23 = __floats2half2_rn(v[j].z * inv, v[j].w * inv);
        uint2 hv; hv.x = *(uint32_t*)&h01; hv.y = *(uint32_t*)&h23;
        *(uint2*)(o + (lane + 32 * j) * 4) = hv;
    }
}

// feature softmax (768), warp per row, fp32 out.
__global__ void __launch_bounds__(256)
softmax768_kernel(const float* __restrict__ O, float* __restrict__ out)
{
    const int wid = threadIdx.x >> 5, lane = threadIdx.x & 31;
    const long row = (long)blockIdx.x * 8 + wid;
    const float* p = O + row * D_;
    float* q = out + row * D_;

    float4 v[6];
    float m = -3.4e38f;
    #pragma unroll
    for (int j = 0; j < 6; j++) {
        v[j] = ((const float4*)p)[lane + 32 * j];
        m = fmaxf(m, fmaxf(fmaxf(v[j].x, v[j].y), fmaxf(v[j].z, v[j].w)));
    }
    m = warp_max(m);
    float s = 0.f;
    #pragma unroll
    for (int j = 0; j < 6; j++) {
        v[j].x = __expf(v[j].x - m); v[j].y = __expf(v[j].y - m);
        v[j].z = __expf(v[j].z - m); v[j].w = __expf(v[j].w - m);
        s += v[j].x + v[j].y + v[j].z + v[j].w;
    }
    float inv = 1.0f / warp_sum(s);
    #pragma unroll
    for (int j = 0; j < 6; j++) {
        float4 r = make_float4(v[j].x * inv, v[j].y * inv, v[j].z * inv, v[j].w * inv);
        ((float4*)q)[lane + 32 * j] = r;
    }
}

// ======================= launch ===========================================
extern "C" void kernel_launch(void* const* d_in, const int* in_sizes, int n_in,
                              void* d_out, int out_size)
{
    const float* Q     = (const float*)d_in[0];
    const float* K     = (const float*)d_in[1];
    const float* V     = (const float*)d_in[2];
    const float* Wq    = (const float*)d_in[3];
    const float* Wk    = (const float*)d_in[4];
    const float* Wv    = (const float*)d_in[5];
    const float* gamma = (const float*)d_in[6];
    const float* beta  = (const float*)d_in[7];
    float* out = (float*)d_out;

    h16 *x16, *w16, *q16, *k16, *vT16, *p16;
    float *gq, *gk, *gs;
    cudaGetSymbolAddress((void**)&x16,  g_x16);
    cudaGetSymbolAddress((void**)&w16,  g_w16);
    cudaGetSymbolAddress((void**)&q16,  g_q16);
    cudaGetSymbolAddress((void**)&k16,  g_k16);
    cudaGetSymbolAddress((void**)&vT16, g_vT16);
    cudaGetSymbolAddress((void**)&p16,  g_p16);
    cudaGetSymbolAddress((void**)&gq,   g_q);
    cudaGetSymbolAddress((void**)&gk,   g_k);
    cudaGetSymbolAddress((void**)&gs,   g_s);
    float* go = gq;   // O reuses q-projection buffer (dead after LN)

    cudaFuncSetAttribute(hgemm,     cudaFuncAttributeMaxDynamicSharedMemorySize, SMEMSZ);
    cudaFuncSetAttribute(proj_gemm, cudaFuncAttributeMaxDynamicSharedMemorySize, SMEMSZ);

    const dim3 blk(256);
    const float scale = 1.0f / sqrtf((float)D_);
    const int gX = (MTOT * (D_ / 4) + 255) / 256;
    const int gW = (D_ * (D_ / 4) + 255) / 256;

    // 0. gather+cvt X; cvt W (fp16 operand planes)
    gather_cvt<<<dim3(gX, 3), blk>>>(Q, K, V, x16);
    w_cvt<<<dim3(gW, 3), blk>>>(Wq, Wk, Wv, w16);

    // 1. merged projections (z in {q,k,v}), fp16 operands, cp.async pipeline
    proj_gemm<<<dim3(D_ / BN, MTOT / BM, 3), blk, SMEMSZ>>>(x16, w16, gq, gk, vT16);

    // 2. merged LN (warp-per-row) -> fp16 q16/k16
    ln_kernel<<<dim3(MTOT / 8, 2), blk>>>(gq, gk, q16, k16, gamma, beta);

    // 3. S = q k^T * scale (per batch)
    hgemm<<<dim3(LS_ / BN, LS_ / BM, B_), blk, SMEMSZ>>>(
        q16, k16, gs, D_, scale,
        (long)LS_ * D_, (long)LS_ * D_, (long)LS_ * LS_, D_, D_, LS_);

    // 4. row softmax (warp-per-row) -> fp16 P
    softmax2048_kernel<<<B_ * LS_ / 8, blk>>>(gs, p16);

    // 5. O = P v (fp16 operands, K=2048)
    hgemm<<<dim3(D_ / BN, LS_ / BM, B_), blk, SMEMSZ>>>(
        p16, vT16, go, LS_, 1.0f,
        (long)LS_ * LS_, (long)D_ * LS_, (long)LS_ * D_, LS_, LS_, D_);

    // 6. feature softmax (warp-per-row) -> out
    softmax768_kernel<<<MTOT / 8, blk>>>(go, out);
}